// round 8
// baseline (speedup 1.0000x reference)
#include <cuda_runtime.h>
#include <cuda_bf16.h>
#include <cstdint>

#define B_    4
#define T_    4096
#define D_    1024
#define H_    16
#define DH_   64
#define NS_   4
#define CTX_  516
#define Q0_   3580
#define MTOT_ (B_*CTX_)   // 2064
#define XR_   520         // per-batch gathered x rows: 4 sinks + 516 window

// ---------------------------------------------------------------------------
// Device scratch (no allocation allowed)
// ---------------------------------------------------------------------------
__device__ __align__(16) __nv_bfloat16 g_Xh[B_*XR_*D_];
__device__ __align__(16) __nv_bfloat16 g_Xl[B_*XR_*D_];
__device__ __align__(16) __nv_bfloat16 g_Wth[4*D_*D_];   // W^T hi: [z][n][k]
__device__ __align__(16) __nv_bfloat16 g_Wtl[4*D_*D_];   // W^T lo
__device__ __align__(16) float g_Q[MTOT_*D_];
__device__ __align__(16) float g_K[MTOT_*D_];
__device__ __align__(16) float g_V[MTOT_*D_];
__device__ __align__(16) __nv_bfloat16 g_AOh[MTOT_*D_];
__device__ __align__(16) __nv_bfloat16 g_AOl[MTOT_*D_];

// ---------------------------------------------------------------------------
__device__ __forceinline__ uint32_t smem_u32(const void* p) {
    uint32_t a;
    asm("{ .reg .u64 t; cvta.to.shared.u64 t, %1; cvt.u32.u64 %0, t; }" : "=r"(a) : "l"(p));
    return a;
}
__device__ __forceinline__ uint32_t pack_bf2(float a, float b) {
    return ((uint32_t)__bfloat16_as_ushort(__float2bfloat16_rn(b)) << 16) |
           (uint32_t)__bfloat16_as_ushort(__float2bfloat16_rn(a));
}
__device__ __forceinline__ void ldsm4(uint32_t* r, uint32_t addr) {
    asm volatile("ldmatrix.sync.aligned.m8n8.x4.shared.b16 {%0,%1,%2,%3}, [%4];"
        : "=r"(r[0]), "=r"(r[1]), "=r"(r[2]), "=r"(r[3]) : "r"(addr));
}
__device__ __forceinline__ void ldsm2(uint32_t* r, uint32_t addr) {
    asm volatile("ldmatrix.sync.aligned.m8n8.x2.shared.b16 {%0,%1}, [%2];"
        : "=r"(r[0]), "=r"(r[1]) : "r"(addr));
}
__device__ __forceinline__ void mma16816(float* c, const uint32_t* a, const uint32_t* b) {
    asm volatile(
        "mma.sync.aligned.m16n8k16.row.col.f32.bf16.bf16.f32 "
        "{%0,%1,%2,%3}, {%4,%5,%6,%7}, {%8,%9}, {%0,%1,%2,%3};"
        : "+f"(c[0]), "+f"(c[1]), "+f"(c[2]), "+f"(c[3])
        : "r"(a[0]), "r"(a[1]), "r"(a[2]), "r"(a[3]), "r"(b[0]), "r"(b[1]));
}
__device__ __forceinline__ void cpa16(uint32_t dst, const void* src, bool valid) {
    int sz = valid ? 16 : 0;
    asm volatile("cp.async.cg.shared.global [%0], [%1], 16, %2;"
        :: "r"(dst), "l"(src), "r"(sz) : "memory");
}
#define CPA_COMMIT() asm volatile("cp.async.commit_group;" ::: "memory")
#define CPA_WAIT(n)  asm volatile("cp.async.wait_group %0;" :: "n"(n) : "memory")

// ---------------------------------------------------------------------------
// Zero-fill the structurally-zero output rows
// ---------------------------------------------------------------------------
__global__ void zero_kernel(float* __restrict__ out) {
    size_t idx = (size_t)blockIdx.x * blockDim.x + threadIdx.x;
    const size_t n4 = (size_t)B_ * Q0_ * D_ / 4;
    if (idx < n4) {
        size_t e = idx * 4;
        const size_t perb = (size_t)Q0_ * D_;
        size_t b = e / perb, r = e % perb;
        *(float4*)(out + b * (size_t)T_ * D_ + r) = make_float4(0.f, 0.f, 0.f, 0.f);
    }
}

// ---------------------------------------------------------------------------
// prep_x: gather live x rows, split fp32 -> bf16 hi/lo
// ---------------------------------------------------------------------------
__global__ __launch_bounds__(256) void prep_x(const float* __restrict__ x) {
    int gr = blockIdx.x;            // 0..2079
    int b = gr / XR_, r = gr % XR_;
    int tok = (r < NS_) ? r : (Q0_ + (r - NS_));
    int t = threadIdx.x;
    float4 v = *(const float4*)(x + (size_t)(b * T_ + tok) * D_ + t * 4);
    float h0 = __bfloat162float(__float2bfloat16_rn(v.x));
    float h1 = __bfloat162float(__float2bfloat16_rn(v.y));
    float h2 = __bfloat162float(__float2bfloat16_rn(v.z));
    float h3 = __bfloat162float(__float2bfloat16_rn(v.w));
    uint2 hw = make_uint2(pack_bf2(v.x, v.y), pack_bf2(v.z, v.w));
    uint2 lw = make_uint2(pack_bf2(v.x - h0, v.y - h1), pack_bf2(v.z - h2, v.w - h3));
    ((uint2*)g_Xh)[(size_t)gr * 256 + t] = hw;
    ((uint2*)g_Xl)[(size_t)gr * 256 + t] = lw;
}

// ---------------------------------------------------------------------------
// prep_w: transpose W (4 matrices) -> [n][k] bf16 hi/lo
// ---------------------------------------------------------------------------
__global__ __launch_bounds__(256) void prep_w(
    const float* __restrict__ Wq, const float* __restrict__ Wk,
    const float* __restrict__ Wv, const float* __restrict__ Wo)
{
    const int z = blockIdx.z;
    const float* __restrict__ W = (z == 0) ? Wq : (z == 1) ? Wk : (z == 2) ? Wv : Wo;
    __shared__ float tile[64][33];
    const int n0 = blockIdx.x * 32, k0 = blockIdx.y * 64;
    const int tx = threadIdx.x, ty = threadIdx.y;

    #pragma unroll
    for (int rr = 0; rr < 8; rr++) {
        int kk = ty + rr * 8;
        tile[kk][tx] = W[(size_t)(k0 + kk) * D_ + n0 + tx];
    }
    __syncthreads();
    #pragma unroll
    for (int rr = 0; rr < 4; rr++) {
        int n = ty + rr * 8;
        float v0 = tile[tx * 2][n], v1 = tile[tx * 2 + 1][n];
        float h0 = __bfloat162float(__float2bfloat16_rn(v0));
        float h1 = __bfloat162float(__float2bfloat16_rn(v1));
        size_t base = (size_t)z * D_ * D_ + (size_t)(n0 + n) * D_ + k0;
        ((uint32_t*)(g_Wth + base))[tx] = pack_bf2(v0, v1);
        ((uint32_t*)(g_Wtl + base))[tx] = pack_bf2(v0 - h0, v1 - h1);
    }
}

// ---------------------------------------------------------------------------
// Tensor-core GEMM via mma.sync + cp.async 2-stage pipeline. (unchanged R6)
// ---------------------------------------------------------------------------
#define GM 128
#define GN 128
#define KC 32
#define SPAD 40
#define NCHUNK (D_/KC)                // 32
#define STG  (GM*SPAD)
#define STGB (STG*2)
#define GSMEM (8*STG*2)               // 81920 bytes

__global__ __launch_bounds__(256, 2) void gemm_mma(int mode_base, float* __restrict__ outF) {
    extern __shared__ __nv_bfloat16 ds[];
    __nv_bfloat16* sAh = ds;
    __nv_bfloat16* sAl = ds + 2 * STG;
    __nv_bfloat16* sBh = ds + 4 * STG;
    __nv_bfloat16* sBl = ds + 6 * STG;

    const int mode = mode_base + blockIdx.z;
    const int n0 = blockIdx.x * GN;
    const int m0 = blockIdx.y * GM;
    const int tid = threadIdx.x;
    const int wid = tid >> 5, lane = tid & 31;
    const int warp_m = (wid & 1) * 64;
    const int warp_n = (wid >> 1) * 32;

    const __nv_bfloat16* __restrict__ Bh_g = g_Wth + (size_t)mode * D_ * D_;
    const __nv_bfloat16* __restrict__ Bl_g = g_Wtl + (size_t)mode * D_ * D_;
    const __nv_bfloat16* __restrict__ Ah_g = (mode < 3) ? g_Xh : g_AOh;
    const __nv_bfloat16* __restrict__ Al_g = (mode < 3) ? g_Xl : g_AOl;

    const int ar0 = tid >> 2, ar1 = ar0 + 64;
    const int q = tid & 3;
    long asrc0 = -1, asrc1 = -1;
    {
        int m = m0 + ar0;
        if (m < MTOT_) {
            if (mode < 3) { int b = m / CTX_, i = m % CTX_; asrc0 = (long)b * XR_ + ((mode == 0) ? (NS_ + i) : ((i < NS_) ? i : (NS_ + i))); }
            else asrc0 = m;
        }
        m = m0 + ar1;
        if (m < MTOT_) {
            if (mode < 3) { int b = m / CTX_, i = m % CTX_; asrc1 = (long)b * XR_ + ((mode == 0) ? (NS_ + i) : ((i < NS_) ? i : (NS_ + i))); }
            else asrc1 = m;
        }
    }
    const int so0 = ar0 * SPAD + q * 8;
    const int so1 = ar1 * SPAD + q * 8;
    const uint32_t dAh0 = smem_u32(sAh + so0), dAh1 = smem_u32(sAh + so1);
    const uint32_t dAl0 = smem_u32(sAl + so0), dAl1 = smem_u32(sAl + so1);
    const uint32_t dBh0 = smem_u32(sBh + so0), dBh1 = smem_u32(sBh + so1);
    const uint32_t dBl0 = smem_u32(sBl + so0), dBl1 = smem_u32(sBl + so1);

    const int a_row = (lane & 15), a_kh = (lane >> 4) << 3;
    const int b_row = (lane & 7),  b_kh = ((lane >> 3) & 1) << 3;
    uint32_t aAh[4], aAl[4], aBh[4], aBl[4];
    #pragma unroll
    for (int mt = 0; mt < 4; mt++) {
        int r = warp_m + mt * 16 + a_row;
        aAh[mt] = smem_u32(sAh + r * SPAD + a_kh);
        aAl[mt] = smem_u32(sAl + r * SPAD + a_kh);
    }
    #pragma unroll
    for (int nt = 0; nt < 4; nt++) {
        int r = warp_n + nt * 8 + b_row;
        aBh[nt] = smem_u32(sBh + r * SPAD + b_kh);
        aBl[nt] = smem_u32(sBl + r * SPAD + b_kh);
    }

    float acc[4][4][4];
    #pragma unroll
    for (int a = 0; a < 4; a++)
        #pragma unroll
        for (int b = 0; b < 4; b++)
            #pragma unroll
            for (int cc = 0; cc < 4; cc++) acc[a][b][cc] = 0.f;

    auto issue = [&](int c) {
        const uint32_t so = (uint32_t)(c & 1) * STGB;
        const size_t koff = (size_t)c * KC + q * 8;
        const size_t a0 = (asrc0 >= 0 ? (size_t)asrc0 : 0) * D_ + koff;
        const size_t a1 = (asrc1 >= 0 ? (size_t)asrc1 : 0) * D_ + koff;
        cpa16(dAh0 + so, Ah_g + a0, asrc0 >= 0);
        cpa16(dAh1 + so, Ah_g + a1, asrc1 >= 0);
        cpa16(dAl0 + so, Al_g + a0, asrc0 >= 0);
        cpa16(dAl1 + so, Al_g + a1, asrc1 >= 0);
        cpa16(dBh0 + so, Bh_g + (size_t)(n0 + ar0) * D_ + koff, true);
        cpa16(dBh1 + so, Bh_g + (size_t)(n0 + ar1) * D_ + koff, true);
        cpa16(dBl0 + so, Bl_g + (size_t)(n0 + ar0) * D_ + koff, true);
        cpa16(dBl1 + so, Bl_g + (size_t)(n0 + ar1) * D_ + koff, true);
        CPA_COMMIT();
    };

    issue(0);
    issue(1);
    for (int c = 0; c < NCHUNK; c++) {
        if (c == NCHUNK - 1) { CPA_WAIT(0); } else { CPA_WAIT(1); }
        __syncthreads();
        const uint32_t so = (uint32_t)(c & 1) * STGB;
        #pragma unroll
        for (int ks = 0; ks < KC * 2; ks += 32) {
            uint32_t fBh[4][2], fBl[4][2];
            #pragma unroll
            for (int nt = 0; nt < 4; nt++) {
                ldsm2(fBh[nt], aBh[nt] + so + ks);
                ldsm2(fBl[nt], aBl[nt] + so + ks);
            }
            #pragma unroll
            for (int mt = 0; mt < 4; mt++) {
                uint32_t fA[4];
                ldsm4(fA, aAh[mt] + so + ks);
                #pragma unroll
                for (int nt = 0; nt < 4; nt++) mma16816(acc[mt][nt], fA, fBh[nt]);
                #pragma unroll
                for (int nt = 0; nt < 4; nt++) mma16816(acc[mt][nt], fA, fBl[nt]);
                ldsm4(fA, aAl[mt] + so + ks);
                #pragma unroll
                for (int nt = 0; nt < 4; nt++) mma16816(acc[mt][nt], fA, fBh[nt]);
            }
        }
        __syncthreads();
        if (c + 2 < NCHUNK) issue(c + 2);
    }

    const int er = lane >> 2, ec = (lane & 3) * 2;
    #pragma unroll
    for (int mt = 0; mt < 4; mt++) {
        #pragma unroll
        for (int half = 0; half < 2; half++) {
            int mm = m0 + warp_m + mt * 16 + er + half * 8;
            if (mm < MTOT_) {
                float* dst;
                if (mode < 3) {
                    float* outp = (mode == 0) ? g_Q : (mode == 1) ? g_K : g_V;
                    dst = outp + (size_t)mm * D_ + n0;
                } else {
                    int b = mm / CTX_, i = mm % CTX_;
                    dst = outF + (size_t)(b * T_ + Q0_ + i) * D_ + n0;
                }
                #pragma unroll
                for (int nt = 0; nt < 4; nt++) {
                    float2 v = make_float2(acc[mt][nt][half * 2], acc[mt][nt][half * 2 + 1]);
                    *(float2*)(dst + warp_n + nt * 8 + ec) = v;
                }
            }
        }
    }
}

// ---------------------------------------------------------------------------
// Attention v3: quad-per-query split-context online softmax.
// 128 threads = 32 queries x 4 subs; sub handles j = sub (mod 4).
// Partial (m,l,acc) merged across the quad with 2 shfl.xor stages.
// ---------------------------------------------------------------------------
#define AQ 32              // queries per block
#define KT 64              // context tile
#define KP 68              // padded row stride (floats): banks d+4j -> conflict-free quads

__global__ __launch_bounds__(128) void attn_kernel() {
    const int b = blockIdx.z, h = blockIdx.y, qt = blockIdx.x;
    const int tid = threadIdx.x;
    const int sub = tid & 3;
    const int qi = qt * AQ + (tid >> 2);
    const bool act = qi < CTX_;

    float qreg[DH_];
    #pragma unroll
    for (int d = 0; d < DH_; d++) qreg[d] = 0.f;
    if (act) {
        const float* qp = g_Q + (size_t)(b * CTX_ + qi) * D_ + h * DH_;
        #pragma unroll
        for (int d = 0; d < DH_; d += 4) {
            float4 v = *(const float4*)(qp + d);
            qreg[d] = v.x; qreg[d + 1] = v.y; qreg[d + 2] = v.z; qreg[d + 3] = v.w;
        }
    }

    float acc[DH_];
    #pragma unroll
    for (int d = 0; d < DH_; d++) acc[d] = 0.f;
    float mval = -1e30f, lsum = 0.f;

    __shared__ float Ks[KT][KP];
    __shared__ float Vs[KT][KP];

    const int jmax = min(CTX_ - 1, qt * AQ + AQ - 1);
    for (int j0 = 0; j0 <= jmax; j0 += KT) {
        // Stage tile: 128 threads x (KT*DH/4 = 1024 float4s) -> 8 iters
        for (int it = tid; it < KT * DH_ / 4; it += 128) {
            int jj = it >> 4;
            int dd = (it & 15) * 4;
            int j = j0 + jj;
            float4 kv = make_float4(0.f, 0.f, 0.f, 0.f);
            float4 vv = make_float4(0.f, 0.f, 0.f, 0.f);
            if (j < CTX_) {
                size_t off = (size_t)(b * CTX_ + j) * D_ + h * DH_ + dd;
                kv = *(const float4*)(g_K + off);
                vv = *(const float4*)(g_V + off);
            }
            *(float4*)&Ks[jj][dd] = kv;
            *(float4*)&Vs[jj][dd] = vv;
        }
        __syncthreads();

        // each sub covers j = j0 + sub, j0 + sub + 4, ... while j <= qi
        int jend = act ? min(KT, qi - j0 + 1) : 0;
        for (int jj = sub; jj < jend; jj += 4) {
            const float* kr = &Ks[jj][0];
            float s0 = 0.f, s1 = 0.f, s2 = 0.f, s3 = 0.f;
            #pragma unroll
            for (int d = 0; d < DH_; d += 4) {
                float4 kv = *(const float4*)(kr + d);
                s0 += qreg[d + 0] * kv.x;
                s1 += qreg[d + 1] * kv.y;
                s2 += qreg[d + 2] * kv.z;
                s3 += qreg[d + 3] * kv.w;
            }
            float s = ((s0 + s1) + (s2 + s3)) * 0.125f;
            const float* vr = &Vs[jj][0];
            if (s <= mval) {
                float p = __expf(s - mval);
                lsum += p;
                #pragma unroll
                for (int d = 0; d < DH_; d += 4) {
                    float4 vv = *(const float4*)(vr + d);
                    acc[d] += p * vv.x; acc[d + 1] += p * vv.y;
                    acc[d + 2] += p * vv.z; acc[d + 3] += p * vv.w;
                }
            } else {
                float cc = __expf(mval - s);
                mval = s;
                lsum = lsum * cc + 1.f;
                #pragma unroll
                for (int d = 0; d < DH_; d += 4) {
                    float4 vv = *(const float4*)(vr + d);
                    acc[d] = acc[d] * cc + vv.x; acc[d + 1] = acc[d + 1] * cc + vv.y;
                    acc[d + 2] = acc[d + 2] * cc + vv.z; acc[d + 3] = acc[d + 3] * cc + vv.w;
                }
            }
        }
        __syncthreads();
    }

    // Merge partials across the quad (lanes differing in bits 0-1)
    #pragma unroll
    for (int off = 1; off <= 2; off <<= 1) {
        float mo = __shfl_xor_sync(0xFFFFFFFFu, mval, off);
        float lo = __shfl_xor_sync(0xFFFFFFFFu, lsum, off);
        float mn = fmaxf(mval, mo);
        float se = __expf(mval - mn);
        float so = __expf(mo - mn);
        lsum = lsum * se + lo * so;
        #pragma unroll
        for (int d = 0; d < DH_; d++) {
            float ao = __shfl_xor_sync(0xFFFFFFFFu, acc[d], off);
            acc[d] = acc[d] * se + ao * so;
        }
        mval = mn;
    }

    if (act) {
        float inv = 1.f / lsum;
        size_t base = (size_t)(b * CTX_ + qi) * D_ + h * DH_;
        // each sub writes its 16-float quarter
        #pragma unroll
        for (int d0 = 0; d0 < 16; d0 += 2) {
            int d = sub * 16 + d0;
            float o0 = acc[d] * inv, o1 = acc[d + 1] * inv;
            float h0 = __bfloat162float(__float2bfloat16_rn(o0));
            float h1 = __bfloat162float(__float2bfloat16_rn(o1));
            *(uint32_t*)(g_AOh + base + d) = pack_bf2(o0, o1);
            *(uint32_t*)(g_AOl + base + d) = pack_bf2(o0 - h0, o1 - h1);
        }
    }
}

// ---------------------------------------------------------------------------
extern "C" void kernel_launch(void* const* d_in, const int* in_sizes, int n_in,
                              void* d_out, int out_size) {
    const float* x  = (const float*)d_in[0];
    const float* Wq = (const float*)d_in[1];
    const float* Wk = (const float*)d_in[2];
    const float* Wv = (const float*)d_in[3];
    const float* Wo = (const float*)d_in[4];
    float* out = (float*)d_out;

    cudaFuncSetAttribute(gemm_mma, cudaFuncAttributeMaxDynamicSharedMemorySize, GSMEM);

    // 1. Zero structurally-zero output rows
    {
        size_t n4 = (size_t)B_ * Q0_ * D_ / 4;
        zero_kernel<<<(int)((n4 + 255) / 256), 256>>>(out);
    }
    // 2. Prep: gather+split x rows; transpose+split weights
    prep_x<<<B_ * XR_, 256>>>(x);
    prep_w<<<dim3(D_ / 32, D_ / 64, 4), dim3(32, 8)>>>(Wq, Wk, Wv, Wo);

    // 3. Q/K/V projections on tensor cores (modes 0,1,2)
    gemm_mma<<<dim3(D_ / GN, (MTOT_ + GM - 1) / GM, 3), 256, GSMEM>>>(0, nullptr);

    // 4. Attention (quad-per-query)
    attn_kernel<<<dim3((CTX_ + AQ - 1) / AQ, H_, B_), 128>>>();

    // 5. Output projection (mode 3), scattered to live rows
    gemm_mma<<<dim3(D_ / GN, (MTOT_ + GM - 1) / GM, 1), 256, GSMEM>>>(3, out);
}

// round 9
// speedup vs baseline: 1.1408x; 1.1408x over previous
#include <cuda_runtime.h>
#include <cuda_bf16.h>
#include <cstdint>

#define B_    4
#define T_    4096
#define D_    1024
#define H_    16
#define DH_   64
#define NS_   4
#define CTX_  516
#define Q0_   3580
#define MTOT_ (B_*CTX_)   // 2064
#define XR_   520         // per-batch gathered x rows: 4 sinks + 516 window

// ---------------------------------------------------------------------------
// Device scratch (no allocation allowed)
// ---------------------------------------------------------------------------
__device__ __align__(16) __nv_bfloat16 g_Xh[B_*XR_*D_];
__device__ __align__(16) __nv_bfloat16 g_Xl[B_*XR_*D_];
__device__ __align__(16) __nv_bfloat16 g_Wth[4*D_*D_];   // W^T hi: [z][n][k]
__device__ __align__(16) __nv_bfloat16 g_Wtl[4*D_*D_];   // W^T lo
__device__ __align__(16) float g_Q[MTOT_*D_];
__device__ __align__(16) float g_K[MTOT_*D_];
__device__ __align__(16) float g_V[MTOT_*D_];
__device__ __align__(16) __nv_bfloat16 g_AOh[MTOT_*D_];
__device__ __align__(16) __nv_bfloat16 g_AOl[MTOT_*D_];

// ---------------------------------------------------------------------------
__device__ __forceinline__ uint32_t smem_u32(const void* p) {
    uint32_t a;
    asm("{ .reg .u64 t; cvta.to.shared.u64 t, %1; cvt.u32.u64 %0, t; }" : "=r"(a) : "l"(p));
    return a;
}
__device__ __forceinline__ uint32_t pack_bf2(float a, float b) {
    return ((uint32_t)__bfloat16_as_ushort(__float2bfloat16_rn(b)) << 16) |
           (uint32_t)__bfloat16_as_ushort(__float2bfloat16_rn(a));
}
__device__ __forceinline__ void ldsm4(uint32_t* r, uint32_t addr) {
    asm volatile("ldmatrix.sync.aligned.m8n8.x4.shared.b16 {%0,%1,%2,%3}, [%4];"
        : "=r"(r[0]), "=r"(r[1]), "=r"(r[2]), "=r"(r[3]) : "r"(addr));
}
__device__ __forceinline__ void ldsm2(uint32_t* r, uint32_t addr) {
    asm volatile("ldmatrix.sync.aligned.m8n8.x2.shared.b16 {%0,%1}, [%2];"
        : "=r"(r[0]), "=r"(r[1]) : "r"(addr));
}
__device__ __forceinline__ void mma16816(float* c, const uint32_t* a, const uint32_t* b) {
    asm volatile(
        "mma.sync.aligned.m16n8k16.row.col.f32.bf16.bf16.f32 "
        "{%0,%1,%2,%3}, {%4,%5,%6,%7}, {%8,%9}, {%0,%1,%2,%3};"
        : "+f"(c[0]), "+f"(c[1]), "+f"(c[2]), "+f"(c[3])
        : "r"(a[0]), "r"(a[1]), "r"(a[2]), "r"(a[3]), "r"(b[0]), "r"(b[1]));
}
__device__ __forceinline__ void cpa16(uint32_t dst, const void* src, bool valid) {
    int sz = valid ? 16 : 0;
    asm volatile("cp.async.cg.shared.global [%0], [%1], 16, %2;"
        :: "r"(dst), "l"(src), "r"(sz) : "memory");
}
#define CPA_COMMIT() asm volatile("cp.async.commit_group;" ::: "memory")
#define CPA_WAIT(n)  asm volatile("cp.async.wait_group %0;" :: "n"(n) : "memory")

// ---------------------------------------------------------------------------
// Zero-fill the structurally-zero output rows
// ---------------------------------------------------------------------------
__global__ void zero_kernel(float* __restrict__ out) {
    size_t idx = (size_t)blockIdx.x * blockDim.x + threadIdx.x;
    const size_t n4 = (size_t)B_ * Q0_ * D_ / 4;
    if (idx < n4) {
        size_t e = idx * 4;
        const size_t perb = (size_t)Q0_ * D_;
        size_t b = e / perb, r = e % perb;
        *(float4*)(out + b * (size_t)T_ * D_ + r) = make_float4(0.f, 0.f, 0.f, 0.f);
    }
}

// ---------------------------------------------------------------------------
// prep_x: gather live x rows, split fp32 -> bf16 hi/lo
// ---------------------------------------------------------------------------
__global__ __launch_bounds__(256) void prep_x(const float* __restrict__ x) {
    int gr = blockIdx.x;            // 0..2079
    int b = gr / XR_, r = gr % XR_;
    int tok = (r < NS_) ? r : (Q0_ + (r - NS_));
    int t = threadIdx.x;
    float4 v = *(const float4*)(x + (size_t)(b * T_ + tok) * D_ + t * 4);
    float h0 = __bfloat162float(__float2bfloat16_rn(v.x));
    float h1 = __bfloat162float(__float2bfloat16_rn(v.y));
    float h2 = __bfloat162float(__float2bfloat16_rn(v.z));
    float h3 = __bfloat162float(__float2bfloat16_rn(v.w));
    uint2 hw = make_uint2(pack_bf2(v.x, v.y), pack_bf2(v.z, v.w));
    uint2 lw = make_uint2(pack_bf2(v.x - h0, v.y - h1), pack_bf2(v.z - h2, v.w - h3));
    ((uint2*)g_Xh)[(size_t)gr * 256 + t] = hw;
    ((uint2*)g_Xl)[(size_t)gr * 256 + t] = lw;
}

// ---------------------------------------------------------------------------
// prep_w: transpose W (4 matrices) -> [n][k] bf16 hi/lo
// ---------------------------------------------------------------------------
__global__ __launch_bounds__(256) void prep_w(
    const float* __restrict__ Wq, const float* __restrict__ Wk,
    const float* __restrict__ Wv, const float* __restrict__ Wo)
{
    const int z = blockIdx.z;
    const float* __restrict__ W = (z == 0) ? Wq : (z == 1) ? Wk : (z == 2) ? Wv : Wo;
    __shared__ float tile[64][33];
    const int n0 = blockIdx.x * 32, k0 = blockIdx.y * 64;
    const int tx = threadIdx.x, ty = threadIdx.y;

    #pragma unroll
    for (int rr = 0; rr < 8; rr++) {
        int kk = ty + rr * 8;
        tile[kk][tx] = W[(size_t)(k0 + kk) * D_ + n0 + tx];
    }
    __syncthreads();
    #pragma unroll
    for (int rr = 0; rr < 4; rr++) {
        int n = ty + rr * 8;
        float v0 = tile[tx * 2][n], v1 = tile[tx * 2 + 1][n];
        float h0 = __bfloat162float(__float2bfloat16_rn(v0));
        float h1 = __bfloat162float(__float2bfloat16_rn(v1));
        size_t base = (size_t)z * D_ * D_ + (size_t)(n0 + n) * D_ + k0;
        ((uint32_t*)(g_Wth + base))[tx] = pack_bf2(v0, v1);
        ((uint32_t*)(g_Wtl + base))[tx] = pack_bf2(v0 - h0, v1 - h1);
    }
}

// ---------------------------------------------------------------------------
// Tensor-core GEMM via mma.sync + cp.async 2-stage pipeline. (R6, best known)
// ---------------------------------------------------------------------------
#define GM 128
#define GN 128
#define KC 32
#define SPAD 40
#define NCHUNK (D_/KC)                // 32
#define STG  (GM*SPAD)
#define STGB (STG*2)
#define GSMEM (8*STG*2)               // 81920 bytes

__global__ __launch_bounds__(256, 2) void gemm_mma(int mode_base, float* __restrict__ outF) {
    extern __shared__ __nv_bfloat16 ds[];
    __nv_bfloat16* sAh = ds;
    __nv_bfloat16* sAl = ds + 2 * STG;
    __nv_bfloat16* sBh = ds + 4 * STG;
    __nv_bfloat16* sBl = ds + 6 * STG;

    const int mode = mode_base + blockIdx.z;
    const int n0 = blockIdx.x * GN;
    const int m0 = blockIdx.y * GM;
    const int tid = threadIdx.x;
    const int wid = tid >> 5, lane = tid & 31;
    const int warp_m = (wid & 1) * 64;
    const int warp_n = (wid >> 1) * 32;

    const __nv_bfloat16* __restrict__ Bh_g = g_Wth + (size_t)mode * D_ * D_;
    const __nv_bfloat16* __restrict__ Bl_g = g_Wtl + (size_t)mode * D_ * D_;
    const __nv_bfloat16* __restrict__ Ah_g = (mode < 3) ? g_Xh : g_AOh;
    const __nv_bfloat16* __restrict__ Al_g = (mode < 3) ? g_Xl : g_AOl;

    const int ar0 = tid >> 2, ar1 = ar0 + 64;
    const int q = tid & 3;
    long asrc0 = -1, asrc1 = -1;
    {
        int m = m0 + ar0;
        if (m < MTOT_) {
            if (mode < 3) { int b = m / CTX_, i = m % CTX_; asrc0 = (long)b * XR_ + ((mode == 0) ? (NS_ + i) : ((i < NS_) ? i : (NS_ + i))); }
            else asrc0 = m;
        }
        m = m0 + ar1;
        if (m < MTOT_) {
            if (mode < 3) { int b = m / CTX_, i = m % CTX_; asrc1 = (long)b * XR_ + ((mode == 0) ? (NS_ + i) : ((i < NS_) ? i : (NS_ + i))); }
            else asrc1 = m;
        }
    }
    const int so0 = ar0 * SPAD + q * 8;
    const int so1 = ar1 * SPAD + q * 8;
    const uint32_t dAh0 = smem_u32(sAh + so0), dAh1 = smem_u32(sAh + so1);
    const uint32_t dAl0 = smem_u32(sAl + so0), dAl1 = smem_u32(sAl + so1);
    const uint32_t dBh0 = smem_u32(sBh + so0), dBh1 = smem_u32(sBh + so1);
    const uint32_t dBl0 = smem_u32(sBl + so0), dBl1 = smem_u32(sBl + so1);

    const int a_row = (lane & 15), a_kh = (lane >> 4) << 3;
    const int b_row = (lane & 7),  b_kh = ((lane >> 3) & 1) << 3;
    uint32_t aAh[4], aAl[4], aBh[4], aBl[4];
    #pragma unroll
    for (int mt = 0; mt < 4; mt++) {
        int r = warp_m + mt * 16 + a_row;
        aAh[mt] = smem_u32(sAh + r * SPAD + a_kh);
        aAl[mt] = smem_u32(sAl + r * SPAD + a_kh);
    }
    #pragma unroll
    for (int nt = 0; nt < 4; nt++) {
        int r = warp_n + nt * 8 + b_row;
        aBh[nt] = smem_u32(sBh + r * SPAD + b_kh);
        aBl[nt] = smem_u32(sBl + r * SPAD + b_kh);
    }

    float acc[4][4][4];
    #pragma unroll
    for (int a = 0; a < 4; a++)
        #pragma unroll
        for (int b = 0; b < 4; b++)
            #pragma unroll
            for (int cc = 0; cc < 4; cc++) acc[a][b][cc] = 0.f;

    auto issue = [&](int c) {
        const uint32_t so = (uint32_t)(c & 1) * STGB;
        const size_t koff = (size_t)c * KC + q * 8;
        const size_t a0 = (asrc0 >= 0 ? (size_t)asrc0 : 0) * D_ + koff;
        const size_t a1 = (asrc1 >= 0 ? (size_t)asrc1 : 0) * D_ + koff;
        cpa16(dAh0 + so, Ah_g + a0, asrc0 >= 0);
        cpa16(dAh1 + so, Ah_g + a1, asrc1 >= 0);
        cpa16(dAl0 + so, Al_g + a0, asrc0 >= 0);
        cpa16(dAl1 + so, Al_g + a1, asrc1 >= 0);
        cpa16(dBh0 + so, Bh_g + (size_t)(n0 + ar0) * D_ + koff, true);
        cpa16(dBh1 + so, Bh_g + (size_t)(n0 + ar1) * D_ + koff, true);
        cpa16(dBl0 + so, Bl_g + (size_t)(n0 + ar0) * D_ + koff, true);
        cpa16(dBl1 + so, Bl_g + (size_t)(n0 + ar1) * D_ + koff, true);
        CPA_COMMIT();
    };

    issue(0);
    issue(1);
    for (int c = 0; c < NCHUNK; c++) {
        if (c == NCHUNK - 1) { CPA_WAIT(0); } else { CPA_WAIT(1); }
        __syncthreads();
        const uint32_t so = (uint32_t)(c & 1) * STGB;
        #pragma unroll
        for (int ks = 0; ks < KC * 2; ks += 32) {
            uint32_t fBh[4][2], fBl[4][2];
            #pragma unroll
            for (int nt = 0; nt < 4; nt++) {
                ldsm2(fBh[nt], aBh[nt] + so + ks);
                ldsm2(fBl[nt], aBl[nt] + so + ks);
            }
            #pragma unroll
            for (int mt = 0; mt < 4; mt++) {
                uint32_t fA[4];
                ldsm4(fA, aAh[mt] + so + ks);
                #pragma unroll
                for (int nt = 0; nt < 4; nt++) mma16816(acc[mt][nt], fA, fBh[nt]);
                #pragma unroll
                for (int nt = 0; nt < 4; nt++) mma16816(acc[mt][nt], fA, fBl[nt]);
                ldsm4(fA, aAl[mt] + so + ks);
                #pragma unroll
                for (int nt = 0; nt < 4; nt++) mma16816(acc[mt][nt], fA, fBh[nt]);
            }
        }
        __syncthreads();
        if (c + 2 < NCHUNK) issue(c + 2);
    }

    const int er = lane >> 2, ec = (lane & 3) * 2;
    #pragma unroll
    for (int mt = 0; mt < 4; mt++) {
        #pragma unroll
        for (int half = 0; half < 2; half++) {
            int mm = m0 + warp_m + mt * 16 + er + half * 8;
            if (mm < MTOT_) {
                float* dst;
                if (mode < 3) {
                    float* outp = (mode == 0) ? g_Q : (mode == 1) ? g_K : g_V;
                    dst = outp + (size_t)mm * D_ + n0;
                } else {
                    int b = mm / CTX_, i = mm % CTX_;
                    dst = outF + (size_t)(b * T_ + Q0_ + i) * D_ + n0;
                }
                #pragma unroll
                for (int nt = 0; nt < 4; nt++) {
                    float2 v = make_float2(acc[mt][nt][half * 2], acc[mt][nt][half * 2 + 1]);
                    *(float2*)(dst + warp_n + nt * 8 + ec) = v;
                }
            }
        }
    }
}

// ---------------------------------------------------------------------------
// Attention v4: 8 lanes per query, split over head-dim (d-slices).
// Each lane owns 8 of 64 d-components of q and acc; dot via 3-stage
// width-8 shfl butterfly; NO final merge (disjoint slices). 256 threads =
// 8 warps x 4 queries = 32 queries per block.
// ---------------------------------------------------------------------------
#define AQ 32              // queries per block
#define KT 64              // context tile rows

__global__ __launch_bounds__(256) void attn_kernel() {
    const int b = blockIdx.z, h = blockIdx.y, qt = blockIdx.x;
    const int tid = threadIdx.x;
    const int warp = tid >> 5, lane = tid & 31;
    const int sl = lane & 7;             // lane in 8-lane group (d-slice owner)
    const int qi = qt * AQ + warp * 4 + (lane >> 3);
    const bool act = qi < CTX_;
    // highest query this warp handles (for uniform loop bounds)
    const int qi_hi = min(qt * AQ + warp * 4 + 3, CTX_ - 1);

    // q slice: d = sl*8 .. sl*8+7
    float4 qa = make_float4(0.f, 0.f, 0.f, 0.f), qb = qa;
    if (act) {
        const float* qp = g_Q + (size_t)(b * CTX_ + qi) * D_ + h * DH_ + sl * 8;
        qa = *(const float4*)(qp);
        qb = *(const float4*)(qp + 4);
    }

    float a0 = 0.f, a1 = 0.f, a2 = 0.f, a3 = 0.f;
    float a4 = 0.f, a5 = 0.f, a6 = 0.f, a7 = 0.f;
    float mval = -1e30f, lsum = 0.f;

    __shared__ float Ks[KT][DH_];
    __shared__ float Vs[KT][DH_];

    const int jmax = min(CTX_ - 1, qt * AQ + AQ - 1);
    for (int j0 = 0; j0 <= jmax; j0 += KT) {
        // Stage K/V tile: 1024 float4s over 256 threads -> 4 iters
        for (int it = tid; it < KT * DH_ / 4; it += 256) {
            int jj = it >> 4;
            int dd = (it & 15) * 4;
            int j = j0 + jj;
            float4 kv = make_float4(0.f, 0.f, 0.f, 0.f);
            float4 vv = make_float4(0.f, 0.f, 0.f, 0.f);
            if (j < CTX_) {
                size_t off = (size_t)(b * CTX_ + j) * D_ + h * DH_ + dd;
                kv = *(const float4*)(g_K + off);
                vv = *(const float4*)(g_V + off);
            }
            *(float4*)&Ks[jj][dd] = kv;
            *(float4*)&Vs[jj][dd] = vv;
        }
        __syncthreads();

        const int jend = min(KT, qi - j0 + 1);        // per-group true bound
        const int jend_w = min(KT, qi_hi - j0 + 1);   // warp-uniform bound
        for (int jj = 0; jj < jend_w; jj++) {
            const float* kr = &Ks[jj][sl * 8];
            float4 k0 = *(const float4*)(kr);
            float4 k1 = *(const float4*)(kr + 4);
            float s = qa.x * k0.x + qa.y * k0.y + qa.z * k0.z + qa.w * k0.w
                    + qb.x * k1.x + qb.y * k1.y + qb.z * k1.z + qb.w * k1.w;
            // butterfly sum within the 8-lane group (full-mask: all lanes active)
            s += __shfl_xor_sync(0xFFFFFFFFu, s, 1, 8);
            s += __shfl_xor_sync(0xFFFFFFFFu, s, 2, 8);
            s += __shfl_xor_sync(0xFFFFFFFFu, s, 4, 8);
            s *= 0.125f;

            if (act && jj < jend) {
                const float* vr = &Vs[jj][sl * 8];
                float4 v0 = *(const float4*)(vr);
                float4 v1 = *(const float4*)(vr + 4);
                if (s <= mval) {
                    float p = __expf(s - mval);
                    lsum += p;
                    a0 += p * v0.x; a1 += p * v0.y; a2 += p * v0.z; a3 += p * v0.w;
                    a4 += p * v1.x; a5 += p * v1.y; a6 += p * v1.z; a7 += p * v1.w;
                } else {
                    float cc = __expf(mval - s);
                    mval = s;
                    lsum = lsum * cc + 1.f;
                    a0 = a0 * cc + v0.x; a1 = a1 * cc + v0.y;
                    a2 = a2 * cc + v0.z; a3 = a3 * cc + v0.w;
                    a4 = a4 * cc + v1.x; a5 = a5 * cc + v1.y;
                    a6 = a6 * cc + v1.z; a7 = a7 * cc + v1.w;
                }
            }
        }
        __syncthreads();
    }

    if (act) {
        float inv = 1.f / lsum;
        float o0 = a0 * inv, o1 = a1 * inv, o2 = a2 * inv, o3 = a3 * inv;
        float o4 = a4 * inv, o5 = a5 * inv, o6 = a6 * inv, o7 = a7 * inv;
        size_t base = (size_t)(b * CTX_ + qi) * D_ + h * DH_ + sl * 8;
        uint4 hv, lv;
        hv.x = pack_bf2(o0, o1); hv.y = pack_bf2(o2, o3);
        hv.z = pack_bf2(o4, o5); hv.w = pack_bf2(o6, o7);
        float t0 = __bfloat162float(__float2bfloat16_rn(o0));
        float t1 = __bfloat162float(__float2bfloat16_rn(o1));
        float t2 = __bfloat162float(__float2bfloat16_rn(o2));
        float t3 = __bfloat162float(__float2bfloat16_rn(o3));
        float t4 = __bfloat162float(__float2bfloat16_rn(o4));
        float t5 = __bfloat162float(__float2bfloat16_rn(o5));
        float t6 = __bfloat162float(__float2bfloat16_rn(o6));
        float t7 = __bfloat162float(__float2bfloat16_rn(o7));
        lv.x = pack_bf2(o0 - t0, o1 - t1); lv.y = pack_bf2(o2 - t2, o3 - t3);
        lv.z = pack_bf2(o4 - t4, o5 - t5); lv.w = pack_bf2(o6 - t6, o7 - t7);
        *(uint4*)(g_AOh + base) = hv;
        *(uint4*)(g_AOl + base) = lv;
    }
}

// ---------------------------------------------------------------------------
extern "C" void kernel_launch(void* const* d_in, const int* in_sizes, int n_in,
                              void* d_out, int out_size) {
    const float* x  = (const float*)d_in[0];
    const float* Wq = (const float*)d_in[1];
    const float* Wk = (const float*)d_in[2];
    const float* Wv = (const float*)d_in[3];
    const float* Wo = (const float*)d_in[4];
    float* out = (float*)d_out;

    cudaFuncSetAttribute(gemm_mma, cudaFuncAttributeMaxDynamicSharedMemorySize, GSMEM);

    // 1. Zero structurally-zero output rows
    {
        size_t n4 = (size_t)B_ * Q0_ * D_ / 4;
        zero_kernel<<<(int)((n4 + 255) / 256), 256>>>(out);
    }
    // 2. Prep: gather+split x rows; transpose+split weights
    prep_x<<<B_ * XR_, 256>>>(x);
    prep_w<<<dim3(D_ / 32, D_ / 64, 4), dim3(32, 8)>>>(Wq, Wk, Wv, Wo);

    // 3. Q/K/V projections on tensor cores (modes 0,1,2)
    gemm_mma<<<dim3(D_ / GN, (MTOT_ + GM - 1) / GM, 3), 256, GSMEM>>>(0, nullptr);

    // 4. Attention (8 lanes per query, d-sliced)
    attn_kernel<<<dim3((CTX_ + AQ - 1) / AQ, H_, B_), 256>>>();

    // 5. Output projection (mode 3), scattered to live rows
    gemm_mma<<<dim3(D_ / GN, (MTOT_ + GM - 1) / GM, 1), 256, GSMEM>>>(3, out);
}

// round 10
// speedup vs baseline: 1.5179x; 1.3305x over previous
#include <cuda_runtime.h>
#include <cuda_bf16.h>
#include <cstdint>

#define B_    4
#define T_    4096
#define D_    1024
#define H_    16
#define DH_   64
#define NS_   4
#define CTX_  516
#define Q0_   3580
#define MTOT_ (B_*CTX_)   // 2064
#define XR_   520         // per-batch gathered x rows: 4 sinks + 516 window

// ---------------------------------------------------------------------------
// Device scratch (no allocation allowed)
// ---------------------------------------------------------------------------
__device__ __align__(16) __nv_bfloat16 g_Xh[B_*XR_*D_];
__device__ __align__(16) __nv_bfloat16 g_Xl[B_*XR_*D_];
__device__ __align__(16) __nv_bfloat16 g_Wth[4*D_*D_];   // W^T hi: [z][n][k]
__device__ __align__(16) __nv_bfloat16 g_Wtl[4*D_*D_];   // W^T lo
__device__ __align__(16) float g_Q[MTOT_*D_];
__device__ __align__(16) float g_K[MTOT_*D_];
__device__ __align__(16) float g_V[MTOT_*D_];
__device__ __align__(16) __nv_bfloat16 g_AOh[MTOT_*D_];
__device__ __align__(16) __nv_bfloat16 g_AOl[MTOT_*D_];

// ---------------------------------------------------------------------------
__device__ __forceinline__ uint32_t smem_u32(const void* p) {
    uint32_t a;
    asm("{ .reg .u64 t; cvta.to.shared.u64 t, %1; cvt.u32.u64 %0, t; }" : "=r"(a) : "l"(p));
    return a;
}
__device__ __forceinline__ uint32_t pack_bf2(float a, float b) {
    return ((uint32_t)__bfloat16_as_ushort(__float2bfloat16_rn(b)) << 16) |
           (uint32_t)__bfloat16_as_ushort(__float2bfloat16_rn(a));
}
__device__ __forceinline__ void ldsm4(uint32_t* r, uint32_t addr) {
    asm volatile("ldmatrix.sync.aligned.m8n8.x4.shared.b16 {%0,%1,%2,%3}, [%4];"
        : "=r"(r[0]), "=r"(r[1]), "=r"(r[2]), "=r"(r[3]) : "r"(addr));
}
__device__ __forceinline__ void ldsm2(uint32_t* r, uint32_t addr) {
    asm volatile("ldmatrix.sync.aligned.m8n8.x2.shared.b16 {%0,%1}, [%2];"
        : "=r"(r[0]), "=r"(r[1]) : "r"(addr));
}
__device__ __forceinline__ void mma16816(float* c, const uint32_t* a, const uint32_t* b) {
    asm volatile(
        "mma.sync.aligned.m16n8k16.row.col.f32.bf16.bf16.f32 "
        "{%0,%1,%2,%3}, {%4,%5,%6,%7}, {%8,%9}, {%0,%1,%2,%3};"
        : "+f"(c[0]), "+f"(c[1]), "+f"(c[2]), "+f"(c[3])
        : "r"(a[0]), "r"(a[1]), "r"(a[2]), "r"(a[3]), "r"(b[0]), "r"(b[1]));
}
__device__ __forceinline__ void cpa16(uint32_t dst, const void* src, bool valid) {
    int sz = valid ? 16 : 0;
    asm volatile("cp.async.cg.shared.global [%0], [%1], 16, %2;"
        :: "r"(dst), "l"(src), "r"(sz) : "memory");
}
#define CPA_COMMIT() asm volatile("cp.async.commit_group;" ::: "memory")
#define CPA_WAIT(n)  asm volatile("cp.async.wait_group %0;" :: "n"(n) : "memory")

// ---------------------------------------------------------------------------
// Zero-fill the structurally-zero output rows
// ---------------------------------------------------------------------------
__global__ void zero_kernel(float* __restrict__ out) {
    size_t idx = (size_t)blockIdx.x * blockDim.x + threadIdx.x;
    const size_t n4 = (size_t)B_ * Q0_ * D_ / 4;
    if (idx < n4) {
        size_t e = idx * 4;
        const size_t perb = (size_t)Q0_ * D_;
        size_t b = e / perb, r = e % perb;
        *(float4*)(out + b * (size_t)T_ * D_ + r) = make_float4(0.f, 0.f, 0.f, 0.f);
    }
}

// ---------------------------------------------------------------------------
// prep_x: gather live x rows, split fp32 -> bf16 hi/lo
// ---------------------------------------------------------------------------
__global__ __launch_bounds__(256) void prep_x(const float* __restrict__ x) {
    int gr = blockIdx.x;            // 0..2079
    int b = gr / XR_, r = gr % XR_;
    int tok = (r < NS_) ? r : (Q0_ + (r - NS_));
    int t = threadIdx.x;
    float4 v = *(const float4*)(x + (size_t)(b * T_ + tok) * D_ + t * 4);
    float h0 = __bfloat162float(__float2bfloat16_rn(v.x));
    float h1 = __bfloat162float(__float2bfloat16_rn(v.y));
    float h2 = __bfloat162float(__float2bfloat16_rn(v.z));
    float h3 = __bfloat162float(__float2bfloat16_rn(v.w));
    uint2 hw = make_uint2(pack_bf2(v.x, v.y), pack_bf2(v.z, v.w));
    uint2 lw = make_uint2(pack_bf2(v.x - h0, v.y - h1), pack_bf2(v.z - h2, v.w - h3));
    ((uint2*)g_Xh)[(size_t)gr * 256 + t] = hw;
    ((uint2*)g_Xl)[(size_t)gr * 256 + t] = lw;
}

// ---------------------------------------------------------------------------
// prep_w: transpose W (4 matrices) -> [n][k] bf16 hi/lo
// ---------------------------------------------------------------------------
__global__ __launch_bounds__(256) void prep_w(
    const float* __restrict__ Wq, const float* __restrict__ Wk,
    const float* __restrict__ Wv, const float* __restrict__ Wo)
{
    const int z = blockIdx.z;
    const float* __restrict__ W = (z == 0) ? Wq : (z == 1) ? Wk : (z == 2) ? Wv : Wo;
    __shared__ float tile[64][33];
    const int n0 = blockIdx.x * 32, k0 = blockIdx.y * 64;
    const int tx = threadIdx.x, ty = threadIdx.y;

    #pragma unroll
    for (int rr = 0; rr < 8; rr++) {
        int kk = ty + rr * 8;
        tile[kk][tx] = W[(size_t)(k0 + kk) * D_ + n0 + tx];
    }
    __syncthreads();
    #pragma unroll
    for (int rr = 0; rr < 4; rr++) {
        int n = ty + rr * 8;
        float v0 = tile[tx * 2][n], v1 = tile[tx * 2 + 1][n];
        float h0 = __bfloat162float(__float2bfloat16_rn(v0));
        float h1 = __bfloat162float(__float2bfloat16_rn(v1));
        size_t base = (size_t)z * D_ * D_ + (size_t)(n0 + n) * D_ + k0;
        ((uint32_t*)(g_Wth + base))[tx] = pack_bf2(v0, v1);
        ((uint32_t*)(g_Wtl + base))[tx] = pack_bf2(v0 - h0, v1 - h1);
    }
}

// ---------------------------------------------------------------------------
// Tensor-core GEMM via mma.sync + cp.async 2-stage pipeline. (R6, best known)
// ---------------------------------------------------------------------------
#define GM 128
#define GN 128
#define KC 32
#define SPAD 40
#define NCHUNK (D_/KC)                // 32
#define STG  (GM*SPAD)
#define STGB (STG*2)
#define GSMEM (8*STG*2)               // 81920 bytes

__global__ __launch_bounds__(256, 2) void gemm_mma(int mode_base, float* __restrict__ outF) {
    extern __shared__ __nv_bfloat16 ds[];
    __nv_bfloat16* sAh = ds;
    __nv_bfloat16* sAl = ds + 2 * STG;
    __nv_bfloat16* sBh = ds + 4 * STG;
    __nv_bfloat16* sBl = ds + 6 * STG;

    const int mode = mode_base + blockIdx.z;
    const int n0 = blockIdx.x * GN;
    const int m0 = blockIdx.y * GM;
    const int tid = threadIdx.x;
    const int wid = tid >> 5, lane = tid & 31;
    const int warp_m = (wid & 1) * 64;
    const int warp_n = (wid >> 1) * 32;

    const __nv_bfloat16* __restrict__ Bh_g = g_Wth + (size_t)mode * D_ * D_;
    const __nv_bfloat16* __restrict__ Bl_g = g_Wtl + (size_t)mode * D_ * D_;
    const __nv_bfloat16* __restrict__ Ah_g = (mode < 3) ? g_Xh : g_AOh;
    const __nv_bfloat16* __restrict__ Al_g = (mode < 3) ? g_Xl : g_AOl;

    const int ar0 = tid >> 2, ar1 = ar0 + 64;
    const int q = tid & 3;
    long asrc0 = -1, asrc1 = -1;
    {
        int m = m0 + ar0;
        if (m < MTOT_) {
            if (mode < 3) { int b = m / CTX_, i = m % CTX_; asrc0 = (long)b * XR_ + ((mode == 0) ? (NS_ + i) : ((i < NS_) ? i : (NS_ + i))); }
            else asrc0 = m;
        }
        m = m0 + ar1;
        if (m < MTOT_) {
            if (mode < 3) { int b = m / CTX_, i = m % CTX_; asrc1 = (long)b * XR_ + ((mode == 0) ? (NS_ + i) : ((i < NS_) ? i : (NS_ + i))); }
            else asrc1 = m;
        }
    }
    const int so0 = ar0 * SPAD + q * 8;
    const int so1 = ar1 * SPAD + q * 8;
    const uint32_t dAh0 = smem_u32(sAh + so0), dAh1 = smem_u32(sAh + so1);
    const uint32_t dAl0 = smem_u32(sAl + so0), dAl1 = smem_u32(sAl + so1);
    const uint32_t dBh0 = smem_u32(sBh + so0), dBh1 = smem_u32(sBh + so1);
    const uint32_t dBl0 = smem_u32(sBl + so0), dBl1 = smem_u32(sBl + so1);

    const int a_row = (lane & 15), a_kh = (lane >> 4) << 3;
    const int b_row = (lane & 7),  b_kh = ((lane >> 3) & 1) << 3;
    uint32_t aAh[4], aAl[4], aBh[4], aBl[4];
    #pragma unroll
    for (int mt = 0; mt < 4; mt++) {
        int r = warp_m + mt * 16 + a_row;
        aAh[mt] = smem_u32(sAh + r * SPAD + a_kh);
        aAl[mt] = smem_u32(sAl + r * SPAD + a_kh);
    }
    #pragma unroll
    for (int nt = 0; nt < 4; nt++) {
        int r = warp_n + nt * 8 + b_row;
        aBh[nt] = smem_u32(sBh + r * SPAD + b_kh);
        aBl[nt] = smem_u32(sBl + r * SPAD + b_kh);
    }

    float acc[4][4][4];
    #pragma unroll
    for (int a = 0; a < 4; a++)
        #pragma unroll
        for (int b = 0; b < 4; b++)
            #pragma unroll
            for (int cc = 0; cc < 4; cc++) acc[a][b][cc] = 0.f;

    auto issue = [&](int c) {
        const uint32_t so = (uint32_t)(c & 1) * STGB;
        const size_t koff = (size_t)c * KC + q * 8;
        const size_t a0 = (asrc0 >= 0 ? (size_t)asrc0 : 0) * D_ + koff;
        const size_t a1 = (asrc1 >= 0 ? (size_t)asrc1 : 0) * D_ + koff;
        cpa16(dAh0 + so, Ah_g + a0, asrc0 >= 0);
        cpa16(dAh1 + so, Ah_g + a1, asrc1 >= 0);
        cpa16(dAl0 + so, Al_g + a0, asrc0 >= 0);
        cpa16(dAl1 + so, Al_g + a1, asrc1 >= 0);
        cpa16(dBh0 + so, Bh_g + (size_t)(n0 + ar0) * D_ + koff, true);
        cpa16(dBh1 + so, Bh_g + (size_t)(n0 + ar1) * D_ + koff, true);
        cpa16(dBl0 + so, Bl_g + (size_t)(n0 + ar0) * D_ + koff, true);
        cpa16(dBl1 + so, Bl_g + (size_t)(n0 + ar1) * D_ + koff, true);
        CPA_COMMIT();
    };

    issue(0);
    issue(1);
    for (int c = 0; c < NCHUNK; c++) {
        if (c == NCHUNK - 1) { CPA_WAIT(0); } else { CPA_WAIT(1); }
        __syncthreads();
        const uint32_t so = (uint32_t)(c & 1) * STGB;
        #pragma unroll
        for (int ks = 0; ks < KC * 2; ks += 32) {
            uint32_t fBh[4][2], fBl[4][2];
            #pragma unroll
            for (int nt = 0; nt < 4; nt++) {
                ldsm2(fBh[nt], aBh[nt] + so + ks);
                ldsm2(fBl[nt], aBl[nt] + so + ks);
            }
            #pragma unroll
            for (int mt = 0; mt < 4; mt++) {
                uint32_t fA[4];
                ldsm4(fA, aAh[mt] + so + ks);
                #pragma unroll
                for (int nt = 0; nt < 4; nt++) mma16816(acc[mt][nt], fA, fBh[nt]);
                #pragma unroll
                for (int nt = 0; nt < 4; nt++) mma16816(acc[mt][nt], fA, fBl[nt]);
                ldsm4(fA, aAl[mt] + so + ks);
                #pragma unroll
                for (int nt = 0; nt < 4; nt++) mma16816(acc[mt][nt], fA, fBh[nt]);
            }
        }
        __syncthreads();
        if (c + 2 < NCHUNK) issue(c + 2);
    }

    const int er = lane >> 2, ec = (lane & 3) * 2;
    #pragma unroll
    for (int mt = 0; mt < 4; mt++) {
        #pragma unroll
        for (int half = 0; half < 2; half++) {
            int mm = m0 + warp_m + mt * 16 + er + half * 8;
            if (mm < MTOT_) {
                float* dst;
                if (mode < 3) {
                    float* outp = (mode == 0) ? g_Q : (mode == 1) ? g_K : g_V;
                    dst = outp + (size_t)mm * D_ + n0;
                } else {
                    int b = mm / CTX_, i = mm % CTX_;
                    dst = outF + (size_t)(b * T_ + Q0_ + i) * D_ + n0;
                }
                #pragma unroll
                for (int nt = 0; nt < 4; nt++) {
                    float2 v = make_float2(acc[mt][nt][half * 2], acc[mt][nt][half * 2 + 1]);
                    *(float2*)(dst + warp_n + nt * 8 + ec) = v;
                }
            }
        }
    }
}

// ---------------------------------------------------------------------------
// Attention v5: one thread per query (no inner-loop cross-lane ops),
// 4-way j-batching for ILP, warp-chunk striping for block balance.
// 17 chunks of 32 queries dealt to 5 blocks: block p owns {p, p+5, p+10, p+15}.
// ---------------------------------------------------------------------------
#define NCHK 17            // ceil(CTX/32)
#define NBLK 5
#define KT  64             // context tile rows (logical)
#define KTP 68             // staged rows (allows 4-wide over-read, masked)
#define MASKV (-3.0e38f)   // mask value; MUST be << init mval (-1e30)

__global__ __launch_bounds__(128) void attn_kernel() {
    const int b = blockIdx.z, h = blockIdx.y, p = blockIdx.x;
    const int tid = threadIdx.x;
    const int warp = tid >> 5, lane = tid & 31;
    const int chunk = p + NBLK * warp;
    const bool vchunk = chunk < NCHK;
    const int qi = chunk * 32 + lane;
    const bool act = vchunk && qi < CTX_;
    const int qi_w_max = vchunk ? min(chunk * 32 + 31, CTX_ - 1) : -1;

    // block-level max context needed
    int cmax = p + NBLK * 3;
    if (cmax >= NCHK) cmax -= NBLK;
    const int jmax_blk = min(cmax * 32 + 31, CTX_ - 1);

    float qreg[DH_];
    #pragma unroll
    for (int d = 0; d < DH_; d++) qreg[d] = 0.f;
    if (act) {
        const float* qp = g_Q + (size_t)(b * CTX_ + qi) * D_ + h * DH_;
        #pragma unroll
        for (int d = 0; d < DH_; d += 4) {
            float4 v = *(const float4*)(qp + d);
            qreg[d] = v.x; qreg[d + 1] = v.y; qreg[d + 2] = v.z; qreg[d + 3] = v.w;
        }
    }

    float acc[DH_];
    #pragma unroll
    for (int d = 0; d < DH_; d++) acc[d] = 0.f;
    float mval = -1e30f, lsum = 0.f;

    __shared__ float Ks[KTP][DH_];
    __shared__ float Vs[KTP][DH_];

    for (int j0 = 0; j0 <= jmax_blk; j0 += KT) {
        // Stage KTP rows (rows beyond CTX zero-filled)
        for (int it = tid; it < KTP * 16; it += 128) {
            int jj = it >> 4;
            int dd = (it & 15) * 4;
            int j = j0 + jj;
            float4 kv = make_float4(0.f, 0.f, 0.f, 0.f);
            float4 vv = make_float4(0.f, 0.f, 0.f, 0.f);
            if (j < CTX_) {
                size_t off = (size_t)(b * CTX_ + j) * D_ + h * DH_ + dd;
                kv = *(const float4*)(g_K + off);
                vv = *(const float4*)(g_V + off);
            }
            *(float4*)&Ks[jj][dd] = kv;
            *(float4*)&Vs[jj][dd] = vv;
        }
        __syncthreads();

        if (vchunk && j0 <= qi_w_max) {
            const int jend   = act ? (qi - j0 + 1 < KT ? qi - j0 + 1 : KT) : 0;   // may be <=0
            const int jend_w = min(KT, qi_w_max - j0 + 1);
            for (int jj0 = 0; jj0 < jend_w; jj0 += 4) {
                // 4 independent dots (2 partials each for ILP)
                float s0a = 0.f, s0b = 0.f, s1a = 0.f, s1b = 0.f;
                float s2a = 0.f, s2b = 0.f, s3a = 0.f, s3b = 0.f;
                const float* k0 = &Ks[jj0 + 0][0];
                const float* k1 = &Ks[jj0 + 1][0];
                const float* k2 = &Ks[jj0 + 2][0];
                const float* k3 = &Ks[jj0 + 3][0];
                #pragma unroll
                for (int d = 0; d < DH_; d += 2) {
                    s0a += qreg[d] * k0[d]; s0b += qreg[d + 1] * k0[d + 1];
                    s1a += qreg[d] * k1[d]; s1b += qreg[d + 1] * k1[d + 1];
                    s2a += qreg[d] * k2[d]; s2b += qreg[d + 1] * k2[d + 1];
                    s3a += qreg[d] * k3[d]; s3b += qreg[d + 1] * k3[d + 1];
                }
                float s0 = (jj0 + 0 < jend) ? (s0a + s0b) * 0.125f : MASKV;
                float s1 = (jj0 + 1 < jend) ? (s1a + s1b) * 0.125f : MASKV;
                float s2 = (jj0 + 2 < jend) ? (s2a + s2b) * 0.125f : MASKV;
                float s3 = (jj0 + 3 < jend) ? (s3a + s3b) * 0.125f : MASKV;
                float mb = fmaxf(fmaxf(s0, s1), fmaxf(s2, s3));

                const float* v0 = &Vs[jj0 + 0][0];
                const float* v1 = &Vs[jj0 + 1][0];
                const float* v2 = &Vs[jj0 + 2][0];
                const float* v3 = &Vs[jj0 + 3][0];
                if (mb <= mval) {
                    float p0 = __expf(s0 - mval), p1 = __expf(s1 - mval);
                    float p2 = __expf(s2 - mval), p3 = __expf(s3 - mval);
                    lsum += (p0 + p1) + (p2 + p3);
                    #pragma unroll
                    for (int d = 0; d < DH_; d++)
                        acc[d] += p0 * v0[d] + p1 * v1[d] + p2 * v2[d] + p3 * v3[d];
                } else {
                    float cc = __expf(mval - mb);
                    float p0 = __expf(s0 - mb), p1 = __expf(s1 - mb);
                    float p2 = __expf(s2 - mb), p3 = __expf(s3 - mb);
                    lsum = lsum * cc + (p0 + p1) + (p2 + p3);
                    #pragma unroll
                    for (int d = 0; d < DH_; d++)
                        acc[d] = acc[d] * cc + p0 * v0[d] + p1 * v1[d]
                                             + p2 * v2[d] + p3 * v3[d];
                    mval = mb;
                }
            }
        }
        __syncthreads();
    }

    if (act) {
        float inv = 1.f / lsum;
        size_t base = (size_t)(b * CTX_ + qi) * D_ + h * DH_;
        #pragma unroll
        for (int d = 0; d < DH_; d += 2) {
            float o0 = acc[d] * inv, o1 = acc[d + 1] * inv;
            float h0 = __bfloat162float(__float2bfloat16_rn(o0));
            float h1 = __bfloat162float(__float2bfloat16_rn(o1));
            *(uint32_t*)(g_AOh + base + d) = pack_bf2(o0, o1);
            *(uint32_t*)(g_AOl + base + d) = pack_bf2(o0 - h0, o1 - h1);
        }
    }
}

// ---------------------------------------------------------------------------
extern "C" void kernel_launch(void* const* d_in, const int* in_sizes, int n_in,
                              void* d_out, int out_size) {
    const float* x  = (const float*)d_in[0];
    const float* Wq = (const float*)d_in[1];
    const float* Wk = (const float*)d_in[2];
    const float* Wv = (const float*)d_in[3];
    const float* Wo = (const float*)d_in[4];
    float* out = (float*)d_out;

    cudaFuncSetAttribute(gemm_mma, cudaFuncAttributeMaxDynamicSharedMemorySize, GSMEM);

    // 1. Zero structurally-zero output rows
    {
        size_t n4 = (size_t)B_ * Q0_ * D_ / 4;
        zero_kernel<<<(int)((n4 + 255) / 256), 256>>>(out);
    }
    // 2. Prep: gather+split x rows; transpose+split weights
    prep_x<<<B_ * XR_, 256>>>(x);
    prep_w<<<dim3(D_ / 32, D_ / 64, 4), dim3(32, 8)>>>(Wq, Wk, Wv, Wo);

    // 3. Q/K/V projections on tensor cores (modes 0,1,2)
    gemm_mma<<<dim3(D_ / GN, (MTOT_ + GM - 1) / GM, 3), 256, GSMEM>>>(0, nullptr);

    // 4. Attention (thread-per-query, 4-way j-batch, chunk-striped blocks)
    attn_kernel<<<dim3(NBLK, H_, B_), 128>>>();

    // 5. Output projection (mode 3), scattered to live rows
    gemm_mma<<<dim3(D_ / GN, (MTOT_ + GM - 1) / GM, 1), 256, GSMEM>>>(3, out);
}

// round 11
// speedup vs baseline: 2.4992x; 1.6465x over previous
#include <cuda_runtime.h>
#include <cuda_bf16.h>
#include <cstdint>

#define B_    4
#define T_    4096
#define D_    1024
#define H_    16
#define DH_   64
#define NS_   4
#define CTX_  516
#define Q0_   3580
#define MTOT_ (B_*CTX_)   // 2064
#define XR_   520         // per-batch gathered x rows: 4 sinks + 516 window

// ---------------------------------------------------------------------------
// Device scratch (no allocation allowed)
// ---------------------------------------------------------------------------
__device__ __align__(16) __nv_bfloat16 g_Xh[B_*XR_*D_];
__device__ __align__(16) __nv_bfloat16 g_Xl[B_*XR_*D_];
__device__ __align__(16) __nv_bfloat16 g_Wth[4*D_*D_];   // W^T hi: [z][n][k]
__device__ __align__(16) __nv_bfloat16 g_Wtl[4*D_*D_];   // W^T lo
// Q/K/V in bf16 hi/lo (Q pre-scaled by 0.125)
__device__ __align__(16) __nv_bfloat16 g_Qh[MTOT_*D_];
__device__ __align__(16) __nv_bfloat16 g_Ql[MTOT_*D_];
__device__ __align__(16) __nv_bfloat16 g_Kh[MTOT_*D_];
__device__ __align__(16) __nv_bfloat16 g_Kl[MTOT_*D_];
__device__ __align__(16) __nv_bfloat16 g_Vh[MTOT_*D_];
__device__ __align__(16) __nv_bfloat16 g_Vl[MTOT_*D_];
__device__ __align__(16) __nv_bfloat16 g_AOh[MTOT_*D_];
__device__ __align__(16) __nv_bfloat16 g_AOl[MTOT_*D_];

// ---------------------------------------------------------------------------
__device__ __forceinline__ uint32_t smem_u32(const void* p) {
    uint32_t a;
    asm("{ .reg .u64 t; cvta.to.shared.u64 t, %1; cvt.u32.u64 %0, t; }" : "=r"(a) : "l"(p));
    return a;
}
__device__ __forceinline__ uint32_t pack_bf2(float a, float b) {
    return ((uint32_t)__bfloat16_as_ushort(__float2bfloat16_rn(b)) << 16) |
           (uint32_t)__bfloat16_as_ushort(__float2bfloat16_rn(a));
}
__device__ __forceinline__ void ldsm4(uint32_t* r, uint32_t addr) {
    asm volatile("ldmatrix.sync.aligned.m8n8.x4.shared.b16 {%0,%1,%2,%3}, [%4];"
        : "=r"(r[0]), "=r"(r[1]), "=r"(r[2]), "=r"(r[3]) : "r"(addr));
}
__device__ __forceinline__ void ldsm2(uint32_t* r, uint32_t addr) {
    asm volatile("ldmatrix.sync.aligned.m8n8.x2.shared.b16 {%0,%1}, [%2];"
        : "=r"(r[0]), "=r"(r[1]) : "r"(addr));
}
__device__ __forceinline__ void ldsm2t(uint32_t* r, uint32_t addr) {
    asm volatile("ldmatrix.sync.aligned.m8n8.x2.trans.shared.b16 {%0,%1}, [%2];"
        : "=r"(r[0]), "=r"(r[1]) : "r"(addr));
}
__device__ __forceinline__ void mma16816(float* c, const uint32_t* a, const uint32_t* b) {
    asm volatile(
        "mma.sync.aligned.m16n8k16.row.col.f32.bf16.bf16.f32 "
        "{%0,%1,%2,%3}, {%4,%5,%6,%7}, {%8,%9}, {%0,%1,%2,%3};"
        : "+f"(c[0]), "+f"(c[1]), "+f"(c[2]), "+f"(c[3])
        : "r"(a[0]), "r"(a[1]), "r"(a[2]), "r"(a[3]), "r"(b[0]), "r"(b[1]));
}
__device__ __forceinline__ void cpa16(uint32_t dst, const void* src, bool valid) {
    int sz = valid ? 16 : 0;
    asm volatile("cp.async.cg.shared.global [%0], [%1], 16, %2;"
        :: "r"(dst), "l"(src), "r"(sz) : "memory");
}
#define CPA_COMMIT() asm volatile("cp.async.commit_group;" ::: "memory")
#define CPA_WAIT(n)  asm volatile("cp.async.wait_group %0;" :: "n"(n) : "memory")

// ---------------------------------------------------------------------------
__global__ void zero_kernel(float* __restrict__ out) {
    size_t idx = (size_t)blockIdx.x * blockDim.x + threadIdx.x;
    const size_t n4 = (size_t)B_ * Q0_ * D_ / 4;
    if (idx < n4) {
        size_t e = idx * 4;
        const size_t perb = (size_t)Q0_ * D_;
        size_t b = e / perb, r = e % perb;
        *(float4*)(out + b * (size_t)T_ * D_ + r) = make_float4(0.f, 0.f, 0.f, 0.f);
    }
}

// ---------------------------------------------------------------------------
__global__ __launch_bounds__(256) void prep_x(const float* __restrict__ x) {
    int gr = blockIdx.x;
    int b = gr / XR_, r = gr % XR_;
    int tok = (r < NS_) ? r : (Q0_ + (r - NS_));
    int t = threadIdx.x;
    float4 v = *(const float4*)(x + (size_t)(b * T_ + tok) * D_ + t * 4);
    float h0 = __bfloat162float(__float2bfloat16_rn(v.x));
    float h1 = __bfloat162float(__float2bfloat16_rn(v.y));
    float h2 = __bfloat162float(__float2bfloat16_rn(v.z));
    float h3 = __bfloat162float(__float2bfloat16_rn(v.w));
    uint2 hw = make_uint2(pack_bf2(v.x, v.y), pack_bf2(v.z, v.w));
    uint2 lw = make_uint2(pack_bf2(v.x - h0, v.y - h1), pack_bf2(v.z - h2, v.w - h3));
    ((uint2*)g_Xh)[(size_t)gr * 256 + t] = hw;
    ((uint2*)g_Xl)[(size_t)gr * 256 + t] = lw;
}

// ---------------------------------------------------------------------------
__global__ __launch_bounds__(256) void prep_w(
    const float* __restrict__ Wq, const float* __restrict__ Wk,
    const float* __restrict__ Wv, const float* __restrict__ Wo)
{
    const int z = blockIdx.z;
    const float* __restrict__ W = (z == 0) ? Wq : (z == 1) ? Wk : (z == 2) ? Wv : Wo;
    __shared__ float tile[64][33];
    const int n0 = blockIdx.x * 32, k0 = blockIdx.y * 64;
    const int tx = threadIdx.x, ty = threadIdx.y;

    #pragma unroll
    for (int rr = 0; rr < 8; rr++) {
        int kk = ty + rr * 8;
        tile[kk][tx] = W[(size_t)(k0 + kk) * D_ + n0 + tx];
    }
    __syncthreads();
    #pragma unroll
    for (int rr = 0; rr < 4; rr++) {
        int n = ty + rr * 8;
        float v0 = tile[tx * 2][n], v1 = tile[tx * 2 + 1][n];
        float h0 = __bfloat162float(__float2bfloat16_rn(v0));
        float h1 = __bfloat162float(__float2bfloat16_rn(v1));
        size_t base = (size_t)z * D_ * D_ + (size_t)(n0 + n) * D_ + k0;
        ((uint32_t*)(g_Wth + base))[tx] = pack_bf2(v0, v1);
        ((uint32_t*)(g_Wtl + base))[tx] = pack_bf2(v0 - h0, v1 - h1);
    }
}

// ---------------------------------------------------------------------------
// Tensor-core GEMM (R6 engine). modes 0/1/2 -> Q/K/V bf16 hi/lo; mode 3 -> out.
// ---------------------------------------------------------------------------
#define GM 128
#define GN 128
#define KC 32
#define SPAD 40
#define NCHUNK (D_/KC)
#define STG  (GM*SPAD)
#define STGB (STG*2)
#define GSMEM (8*STG*2)               // 81920 bytes

__global__ __launch_bounds__(256, 2) void gemm_mma(int mode_base, float* __restrict__ outF) {
    extern __shared__ __nv_bfloat16 ds[];
    __nv_bfloat16* sAh = ds;
    __nv_bfloat16* sAl = ds + 2 * STG;
    __nv_bfloat16* sBh = ds + 4 * STG;
    __nv_bfloat16* sBl = ds + 6 * STG;

    const int mode = mode_base + blockIdx.z;
    const int n0 = blockIdx.x * GN;
    const int m0 = blockIdx.y * GM;
    const int tid = threadIdx.x;
    const int wid = tid >> 5, lane = tid & 31;
    const int warp_m = (wid & 1) * 64;
    const int warp_n = (wid >> 1) * 32;

    const __nv_bfloat16* __restrict__ Bh_g = g_Wth + (size_t)mode * D_ * D_;
    const __nv_bfloat16* __restrict__ Bl_g = g_Wtl + (size_t)mode * D_ * D_;
    const __nv_bfloat16* __restrict__ Ah_g = (mode < 3) ? g_Xh : g_AOh;
    const __nv_bfloat16* __restrict__ Al_g = (mode < 3) ? g_Xl : g_AOl;

    const int ar0 = tid >> 2, ar1 = ar0 + 64;
    const int q = tid & 3;
    long asrc0 = -1, asrc1 = -1;
    {
        int m = m0 + ar0;
        if (m < MTOT_) {
            if (mode < 3) { int b = m / CTX_, i = m % CTX_; asrc0 = (long)b * XR_ + ((mode == 0) ? (NS_ + i) : ((i < NS_) ? i : (NS_ + i))); }
            else asrc0 = m;
        }
        m = m0 + ar1;
        if (m < MTOT_) {
            if (mode < 3) { int b = m / CTX_, i = m % CTX_; asrc1 = (long)b * XR_ + ((mode == 0) ? (NS_ + i) : ((i < NS_) ? i : (NS_ + i))); }
            else asrc1 = m;
        }
    }
    const int so0 = ar0 * SPAD + q * 8;
    const int so1 = ar1 * SPAD + q * 8;
    const uint32_t dAh0 = smem_u32(sAh + so0), dAh1 = smem_u32(sAh + so1);
    const uint32_t dAl0 = smem_u32(sAl + so0), dAl1 = smem_u32(sAl + so1);
    const uint32_t dBh0 = smem_u32(sBh + so0), dBh1 = smem_u32(sBh + so1);
    const uint32_t dBl0 = smem_u32(sBl + so0), dBl1 = smem_u32(sBl + so1);

    const int a_row = (lane & 15), a_kh = (lane >> 4) << 3;
    const int b_row = (lane & 7),  b_kh = ((lane >> 3) & 1) << 3;
    uint32_t aAh[4], aAl[4], aBh[4], aBl[4];
    #pragma unroll
    for (int mt = 0; mt < 4; mt++) {
        int r = warp_m + mt * 16 + a_row;
        aAh[mt] = smem_u32(sAh + r * SPAD + a_kh);
        aAl[mt] = smem_u32(sAl + r * SPAD + a_kh);
    }
    #pragma unroll
    for (int nt = 0; nt < 4; nt++) {
        int r = warp_n + nt * 8 + b_row;
        aBh[nt] = smem_u32(sBh + r * SPAD + b_kh);
        aBl[nt] = smem_u32(sBl + r * SPAD + b_kh);
    }

    float acc[4][4][4];
    #pragma unroll
    for (int a = 0; a < 4; a++)
        #pragma unroll
        for (int b = 0; b < 4; b++)
            #pragma unroll
            for (int cc = 0; cc < 4; cc++) acc[a][b][cc] = 0.f;

    auto issue = [&](int c) {
        const uint32_t so = (uint32_t)(c & 1) * STGB;
        const size_t koff = (size_t)c * KC + q * 8;
        const size_t a0 = (asrc0 >= 0 ? (size_t)asrc0 : 0) * D_ + koff;
        const size_t a1 = (asrc1 >= 0 ? (size_t)asrc1 : 0) * D_ + koff;
        cpa16(dAh0 + so, Ah_g + a0, asrc0 >= 0);
        cpa16(dAh1 + so, Ah_g + a1, asrc1 >= 0);
        cpa16(dAl0 + so, Al_g + a0, asrc0 >= 0);
        cpa16(dAl1 + so, Al_g + a1, asrc1 >= 0);
        cpa16(dBh0 + so, Bh_g + (size_t)(n0 + ar0) * D_ + koff, true);
        cpa16(dBh1 + so, Bh_g + (size_t)(n0 + ar1) * D_ + koff, true);
        cpa16(dBl0 + so, Bl_g + (size_t)(n0 + ar0) * D_ + koff, true);
        cpa16(dBl1 + so, Bl_g + (size_t)(n0 + ar1) * D_ + koff, true);
        CPA_COMMIT();
    };

    issue(0);
    issue(1);
    for (int c = 0; c < NCHUNK; c++) {
        if (c == NCHUNK - 1) { CPA_WAIT(0); } else { CPA_WAIT(1); }
        __syncthreads();
        const uint32_t so = (uint32_t)(c & 1) * STGB;
        #pragma unroll
        for (int ks = 0; ks < KC * 2; ks += 32) {
            uint32_t fBh[4][2], fBl[4][2];
            #pragma unroll
            for (int nt = 0; nt < 4; nt++) {
                ldsm2(fBh[nt], aBh[nt] + so + ks);
                ldsm2(fBl[nt], aBl[nt] + so + ks);
            }
            #pragma unroll
            for (int mt = 0; mt < 4; mt++) {
                uint32_t fA[4];
                ldsm4(fA, aAh[mt] + so + ks);
                #pragma unroll
                for (int nt = 0; nt < 4; nt++) mma16816(acc[mt][nt], fA, fBh[nt]);
                #pragma unroll
                for (int nt = 0; nt < 4; nt++) mma16816(acc[mt][nt], fA, fBl[nt]);
                ldsm4(fA, aAl[mt] + so + ks);
                #pragma unroll
                for (int nt = 0; nt < 4; nt++) mma16816(acc[mt][nt], fA, fBh[nt]);
            }
        }
        __syncthreads();
        if (c + 2 < NCHUNK) issue(c + 2);
    }

    const int er = lane >> 2, ec = (lane & 3) * 2;
    if (mode < 3) {
        __nv_bfloat16* dh = (mode == 0) ? g_Qh : (mode == 1) ? g_Kh : g_Vh;
        __nv_bfloat16* dl = (mode == 0) ? g_Ql : (mode == 1) ? g_Kl : g_Vl;
        const float scl = (mode == 0) ? 0.125f : 1.0f;   // fold 1/sqrt(dh) into Q (exact)
        #pragma unroll
        for (int mt = 0; mt < 4; mt++) {
            #pragma unroll
            for (int half = 0; half < 2; half++) {
                int mm = m0 + warp_m + mt * 16 + er + half * 8;
                if (mm < MTOT_) {
                    size_t base = (size_t)mm * D_ + n0 + warp_n + ec;
                    #pragma unroll
                    for (int nt = 0; nt < 4; nt++) {
                        float v0 = acc[mt][nt][half * 2] * scl;
                        float v1 = acc[mt][nt][half * 2 + 1] * scl;
                        float t0 = __bfloat162float(__float2bfloat16_rn(v0));
                        float t1 = __bfloat162float(__float2bfloat16_rn(v1));
                        *(uint32_t*)(dh + base + nt * 8) = pack_bf2(v0, v1);
                        *(uint32_t*)(dl + base + nt * 8) = pack_bf2(v0 - t0, v1 - t1);
                    }
                }
            }
        }
    } else {
        #pragma unroll
        for (int mt = 0; mt < 4; mt++) {
            #pragma unroll
            for (int half = 0; half < 2; half++) {
                int mm = m0 + warp_m + mt * 16 + er + half * 8;
                if (mm < MTOT_) {
                    int b = mm / CTX_, i = mm % CTX_;
                    float* dst = outF + (size_t)(b * T_ + Q0_ + i) * D_ + n0;
                    #pragma unroll
                    for (int nt = 0; nt < 4; nt++) {
                        float2 v = make_float2(acc[mt][nt][half * 2], acc[mt][nt][half * 2 + 1]);
                        *(float2*)(dst + warp_n + nt * 8 + ec) = v;
                    }
                }
            }
        }
    }
}

// ---------------------------------------------------------------------------
// Flash attention on mma.sync (bf16 hi/lo). CTA: 64 q-rows x (b,h).
// 4 warps x 16 rows. Context tiles of 64. Causal mask on diagonal tile.
// S = QhKh + QhKl + QlKh ; O += PhVh + PhVl + PlVh ; V^T via ldmatrix.trans.
// ---------------------------------------------------------------------------
#define SST 72    // smem row stride (halves); 144B rows, 16B aligned

__global__ __launch_bounds__(128) void attn_mma() {
    const int b = blockIdx.z, h = blockIdx.y, tau = blockIdx.x;
    const int tid = threadIdx.x, warp = tid >> 5, lane = tid & 31;

    __shared__ __nv_bfloat16 sKh[64 * SST], sKl[64 * SST];
    __shared__ __nv_bfloat16 sVh[64 * SST], sVl[64 * SST];

    const int gq0 = tau * 64 + warp * 16 + (lane >> 2);
    const int gq1 = gq0 + 8;

    // ---- stage Q tile (into sKh/sKl) and extract A-frags ----
    const uint4 zv = make_uint4(0, 0, 0, 0);
    for (int it = tid; it < 64 * 8; it += 128) {
        int row = it >> 3, dd = (it & 7) * 8;
        int gq = tau * 64 + row;
        uint4 vh = zv, vl = zv;
        if (gq < CTX_) {
            size_t off = (size_t)(b * CTX_ + gq) * D_ + h * DH_ + dd;
            vh = *(const uint4*)(g_Qh + off);
            vl = *(const uint4*)(g_Ql + off);
        }
        *(uint4*)(sKh + row * SST + dd) = vh;
        *(uint4*)(sKl + row * SST + dd) = vl;
    }
    __syncthreads();

    uint32_t QhF[4][4], QlF[4][4];
    {
        const uint32_t qoff = (uint32_t)((warp * 16 + (lane & 15)) * (SST * 2) + ((lane >> 4) & 1) * 16);
        const uint32_t bh = smem_u32(sKh) + qoff;
        const uint32_t bl = smem_u32(sKl) + qoff;
        #pragma unroll
        for (int ks = 0; ks < 4; ks++) {
            ldsm4(QhF[ks], bh + ks * 32);
            ldsm4(QlF[ks], bl + ks * 32);
        }
    }

    float oacc[8][4];
    #pragma unroll
    for (int nt = 0; nt < 8; nt++)
        #pragma unroll
        for (int c = 0; c < 4; c++) oacc[nt][c] = 0.f;
    float m0 = -1e30f, m1 = -1e30f, l0 = 0.f, l1 = 0.f;

    // ldsm bases (constant)
    const uint32_t kfo = (uint32_t)((lane & 7) * (SST * 2) + ((lane >> 3) & 1) * 16);
    const uint32_t kbh = smem_u32(sKh) + kfo;
    const uint32_t kbl = smem_u32(sKl) + kfo;
    const uint32_t vfo = (uint32_t)(((lane & 7) + ((lane >> 3) & 1) * 8) * (SST * 2));
    const uint32_t vbh = smem_u32(sVh) + vfo;
    const uint32_t vbl = smem_u32(sVl) + vfo;

    for (int t = 0; t <= tau; t++) {
        __syncthreads();   // previous tile fully consumed (and Q frags extracted)
        for (int it = tid; it < 64 * 8; it += 128) {
            int row = it >> 3, dd = (it & 7) * 8;
            int j = t * 64 + row;
            uint4 kh = zv, kl = zv, vh = zv, vl = zv;
            if (j < CTX_) {
                size_t off = (size_t)(b * CTX_ + j) * D_ + h * DH_ + dd;
                kh = *(const uint4*)(g_Kh + off);
                kl = *(const uint4*)(g_Kl + off);
                vh = *(const uint4*)(g_Vh + off);
                vl = *(const uint4*)(g_Vl + off);
            }
            *(uint4*)(sKh + row * SST + dd) = kh;
            *(uint4*)(sKl + row * SST + dd) = kl;
            *(uint4*)(sVh + row * SST + dd) = vh;
            *(uint4*)(sVl + row * SST + dd) = vl;
        }
        __syncthreads();

        // ---- S = Q K^T (3 hi/lo terms), fp32 accum ----
        float sacc[8][4];
        #pragma unroll
        for (int nt = 0; nt < 8; nt++)
            #pragma unroll
            for (int c = 0; c < 4; c++) sacc[nt][c] = 0.f;

        #pragma unroll
        for (int ks = 0; ks < 4; ks++) {
            #pragma unroll
            for (int nt = 0; nt < 8; nt++) {
                uint32_t fbh[2], fbl[2];
                ldsm2(fbh, kbh + (uint32_t)(nt * 8 * SST * 2 + ks * 32));
                ldsm2(fbl, kbl + (uint32_t)(nt * 8 * SST * 2 + ks * 32));
                mma16816(sacc[nt], QhF[ks], fbh);
                mma16816(sacc[nt], QhF[ks], fbl);
                mma16816(sacc[nt], QlF[ks], fbh);
            }
        }

        // ---- causal mask on diagonal tile ----
        if (t == tau) {
            const int cbase = t * 64 + 2 * (lane & 3);
            #pragma unroll
            for (int nt = 0; nt < 8; nt++) {
                int c0 = cbase + nt * 8, c1 = c0 + 1;
                if (c0 > gq0) sacc[nt][0] = -1e30f;
                if (c1 > gq0) sacc[nt][1] = -1e30f;
                if (c0 > gq1) sacc[nt][2] = -1e30f;
                if (c1 > gq1) sacc[nt][3] = -1e30f;
            }
        }

        // ---- online softmax (rows r0, r1 per thread; quad = lanes sharing row) ----
        float mx0 = -1e30f, mx1 = -1e30f;
        #pragma unroll
        for (int nt = 0; nt < 8; nt++) {
            mx0 = fmaxf(mx0, fmaxf(sacc[nt][0], sacc[nt][1]));
            mx1 = fmaxf(mx1, fmaxf(sacc[nt][2], sacc[nt][3]));
        }
        mx0 = fmaxf(mx0, __shfl_xor_sync(0xFFFFFFFFu, mx0, 1));
        mx0 = fmaxf(mx0, __shfl_xor_sync(0xFFFFFFFFu, mx0, 2));
        mx1 = fmaxf(mx1, __shfl_xor_sync(0xFFFFFFFFu, mx1, 1));
        mx1 = fmaxf(mx1, __shfl_xor_sync(0xFFFFFFFFu, mx1, 2));
        float mn0 = fmaxf(m0, mx0), mn1 = fmaxf(m1, mx1);
        float al0 = __expf(m0 - mn0), al1 = __expf(m1 - mn1);
        m0 = mn0; m1 = mn1;

        float rs0 = 0.f, rs1 = 0.f;
        #pragma unroll
        for (int nt = 0; nt < 8; nt++) {
            float p00 = __expf(sacc[nt][0] - mn0);
            float p01 = __expf(sacc[nt][1] - mn0);
            float p10 = __expf(sacc[nt][2] - mn1);
            float p11 = __expf(sacc[nt][3] - mn1);
            sacc[nt][0] = p00; sacc[nt][1] = p01;
            sacc[nt][2] = p10; sacc[nt][3] = p11;
            rs0 += p00 + p01; rs1 += p10 + p11;
        }
        rs0 += __shfl_xor_sync(0xFFFFFFFFu, rs0, 1);
        rs0 += __shfl_xor_sync(0xFFFFFFFFu, rs0, 2);
        rs1 += __shfl_xor_sync(0xFFFFFFFFu, rs1, 1);
        rs1 += __shfl_xor_sync(0xFFFFFFFFu, rs1, 2);
        l0 = l0 * al0 + rs0;
        l1 = l1 * al1 + rs1;

        #pragma unroll
        for (int nt = 0; nt < 8; nt++) {
            oacc[nt][0] *= al0; oacc[nt][1] *= al0;
            oacc[nt][2] *= al1; oacc[nt][3] *= al1;
        }

        // ---- O += P V (P split hi/lo; V^T B-frags via ldsm.trans) ----
        #pragma unroll
        for (int u = 0; u < 4; u++) {
            // repack P C-frags (tiles 2u, 2u+1) into A-frags hi/lo
            uint32_t Ph[4], Pl[4];
            #pragma unroll
            for (int half = 0; half < 2; half++) {
                const float* pa = sacc[2 * u + half];
                float h0 = __bfloat162float(__float2bfloat16_rn(pa[0]));
                float h1 = __bfloat162float(__float2bfloat16_rn(pa[1]));
                float h2 = __bfloat162float(__float2bfloat16_rn(pa[2]));
                float h3 = __bfloat162float(__float2bfloat16_rn(pa[3]));
                Ph[half * 2 + 0] = pack_bf2(pa[0], pa[1]);   // wait—ordering below
                Ph[half * 2 + 1] = pack_bf2(pa[2], pa[3]);
                Pl[half * 2 + 0] = pack_bf2(pa[0] - h0, pa[1] - h1);
                Pl[half * 2 + 1] = pack_bf2(pa[2] - h2, pa[3] - h3);
            }
            // A-frag order: a0=(r0,k0..1 of tile 2u), a1=(r1, tile 2u), a2=(r0, tile 2u+1), a3=(r1, tile 2u+1)
            // Our fill: half=0 -> Ph[0]=(r0,2u), Ph[1]=(r1,2u); half=1 -> Ph[2]=(r0,2u+1), Ph[3]=(r1,2u+1). Correct.
            #pragma unroll
            for (int nt = 0; nt < 8; nt++) {
                uint32_t fvh[2], fvl[2];
                ldsm2t(fvh, vbh + (uint32_t)(u * 16 * SST * 2 + nt * 16));
                ldsm2t(fvl, vbl + (uint32_t)(u * 16 * SST * 2 + nt * 16));
                mma16816(oacc[nt], Ph, fvh);
                mma16816(oacc[nt], Ph, fvl);
                mma16816(oacc[nt], Pl, fvh);
            }
        }
    }

    // ---- epilogue: normalize and write bf16 hi/lo AO ----
    const int ccol = 2 * (lane & 3);
    if (gq0 < CTX_) {
        float inv = 1.f / l0;
        size_t base = (size_t)(b * CTX_ + gq0) * D_ + h * DH_ + ccol;
        #pragma unroll
        for (int nt = 0; nt < 8; nt++) {
            float v0 = oacc[nt][0] * inv, v1 = oacc[nt][1] * inv;
            float t0 = __bfloat162float(__float2bfloat16_rn(v0));
            float t1 = __bfloat162float(__float2bfloat16_rn(v1));
            *(uint32_t*)(g_AOh + base + nt * 8) = pack_bf2(v0, v1);
            *(uint32_t*)(g_AOl + base + nt * 8) = pack_bf2(v0 - t0, v1 - t1);
        }
    }
    if (gq1 < CTX_) {
        float inv = 1.f / l1;
        size_t base = (size_t)(b * CTX_ + gq1) * D_ + h * DH_ + ccol;
        #pragma unroll
        for (int nt = 0; nt < 8; nt++) {
            float v0 = oacc[nt][2] * inv, v1 = oacc[nt][3] * inv;
            float t0 = __bfloat162float(__float2bfloat16_rn(v0));
            float t1 = __bfloat162float(__float2bfloat16_rn(v1));
            *(uint32_t*)(g_AOh + base + nt * 8) = pack_bf2(v0, v1);
            *(uint32_t*)(g_AOl + base + nt * 8) = pack_bf2(v0 - t0, v1 - t1);
        }
    }
}

// ---------------------------------------------------------------------------
extern "C" void kernel_launch(void* const* d_in, const int* in_sizes, int n_in,
                              void* d_out, int out_size) {
    const float* x  = (const float*)d_in[0];
    const float* Wq = (const float*)d_in[1];
    const float* Wk = (const float*)d_in[2];
    const float* Wv = (const float*)d_in[3];
    const float* Wo = (const float*)d_in[4];
    float* out = (float*)d_out;

    cudaFuncSetAttribute(gemm_mma, cudaFuncAttributeMaxDynamicSharedMemorySize, GSMEM);

    // 1. Zero structurally-zero output rows
    {
        size_t n4 = (size_t)B_ * Q0_ * D_ / 4;
        zero_kernel<<<(int)((n4 + 255) / 256), 256>>>(out);
    }
    // 2. Prep
    prep_x<<<B_ * XR_, 256>>>(x);
    prep_w<<<dim3(D_ / 32, D_ / 64, 4), dim3(32, 8)>>>(Wq, Wk, Wv, Wo);

    // 3. Q/K/V projections -> bf16 hi/lo (Q pre-scaled by 0.125)
    gemm_mma<<<dim3(D_ / GN, (MTOT_ + GM - 1) / GM, 3), 256, GSMEM>>>(0, nullptr);

    // 4. Flash attention on tensor cores
    attn_mma<<<dim3((CTX_ + 63) / 64, H_, B_), 128>>>();

    // 5. Output projection, scattered to live rows
    gemm_mma<<<dim3(D_ / GN, (MTOT_ + GM - 1) / GM, 1), 256, GSMEM>>>(3, out);
}

// round 12
// speedup vs baseline: 2.5955x; 1.0385x over previous
#include <cuda_runtime.h>
#include <cuda_bf16.h>
#include <cstdint>

#define B_    4
#define T_    4096
#define D_    1024
#define H_    16
#define DH_   64
#define NS_   4
#define CTX_  516
#define Q0_   3580
#define MTOT_ (B_*CTX_)   // 2064
#define XR_   520         // per-batch gathered x rows: 4 sinks + 516 window

// ---------------------------------------------------------------------------
// Device scratch (no allocation allowed)
// ---------------------------------------------------------------------------
__device__ __align__(16) __nv_bfloat16 g_Xh[B_*XR_*D_];
__device__ __align__(16) __nv_bfloat16 g_Xl[B_*XR_*D_];
__device__ __align__(16) __nv_bfloat16 g_Wth[4*D_*D_];   // W^T hi: [z][n][k]
__device__ __align__(16) __nv_bfloat16 g_Wtl[4*D_*D_];   // W^T lo
// Q/K/V in bf16 hi/lo (Q pre-scaled by 0.125)
__device__ __align__(16) __nv_bfloat16 g_Qh[MTOT_*D_];
__device__ __align__(16) __nv_bfloat16 g_Ql[MTOT_*D_];
__device__ __align__(16) __nv_bfloat16 g_Kh[MTOT_*D_];
__device__ __align__(16) __nv_bfloat16 g_Kl[MTOT_*D_];
__device__ __align__(16) __nv_bfloat16 g_Vh[MTOT_*D_];
__device__ __align__(16) __nv_bfloat16 g_Vl[MTOT_*D_];
__device__ __align__(16) __nv_bfloat16 g_AOh[MTOT_*D_];
__device__ __align__(16) __nv_bfloat16 g_AOl[MTOT_*D_];

// ---------------------------------------------------------------------------
__device__ __forceinline__ uint32_t smem_u32(const void* p) {
    uint32_t a;
    asm("{ .reg .u64 t; cvta.to.shared.u64 t, %1; cvt.u32.u64 %0, t; }" : "=r"(a) : "l"(p));
    return a;
}
__device__ __forceinline__ uint32_t pack_bf2(float a, float b) {
    return ((uint32_t)__bfloat16_as_ushort(__float2bfloat16_rn(b)) << 16) |
           (uint32_t)__bfloat16_as_ushort(__float2bfloat16_rn(a));
}
__device__ __forceinline__ void ldsm4(uint32_t* r, uint32_t addr) {
    asm volatile("ldmatrix.sync.aligned.m8n8.x4.shared.b16 {%0,%1,%2,%3}, [%4];"
        : "=r"(r[0]), "=r"(r[1]), "=r"(r[2]), "=r"(r[3]) : "r"(addr));
}
__device__ __forceinline__ void ldsm2(uint32_t* r, uint32_t addr) {
    asm volatile("ldmatrix.sync.aligned.m8n8.x2.shared.b16 {%0,%1}, [%2];"
        : "=r"(r[0]), "=r"(r[1]) : "r"(addr));
}
__device__ __forceinline__ void ldsm2t(uint32_t* r, uint32_t addr) {
    asm volatile("ldmatrix.sync.aligned.m8n8.x2.trans.shared.b16 {%0,%1}, [%2];"
        : "=r"(r[0]), "=r"(r[1]) : "r"(addr));
}
__device__ __forceinline__ void mma16816(float* c, const uint32_t* a, const uint32_t* b) {
    asm volatile(
        "mma.sync.aligned.m16n8k16.row.col.f32.bf16.bf16.f32 "
        "{%0,%1,%2,%3}, {%4,%5,%6,%7}, {%8,%9}, {%0,%1,%2,%3};"
        : "+f"(c[0]), "+f"(c[1]), "+f"(c[2]), "+f"(c[3])
        : "r"(a[0]), "r"(a[1]), "r"(a[2]), "r"(a[3]), "r"(b[0]), "r"(b[1]));
}
__device__ __forceinline__ void cpa16(uint32_t dst, const void* src, bool valid) {
    int sz = valid ? 16 : 0;
    asm volatile("cp.async.cg.shared.global [%0], [%1], 16, %2;"
        :: "r"(dst), "l"(src), "r"(sz) : "memory");
}
#define CPA_COMMIT() asm volatile("cp.async.commit_group;" ::: "memory")
#define CPA_WAIT(n)  asm volatile("cp.async.wait_group %0;" :: "n"(n) : "memory")

// ---------------------------------------------------------------------------
// prep_x: gather live x rows, split fp32 -> bf16 hi/lo; also zero-fill the
// structurally-zero output rows (grid-stride tail).
// ---------------------------------------------------------------------------
__global__ __launch_bounds__(256) void prep_x(const float* __restrict__ x,
                                              float* __restrict__ out) {
    int gr = blockIdx.x;
    int b = gr / XR_, r = gr % XR_;
    int tok = (r < NS_) ? r : (Q0_ + (r - NS_));
    int t = threadIdx.x;
    float4 v = *(const float4*)(x + (size_t)(b * T_ + tok) * D_ + t * 4);
    float h0 = __bfloat162float(__float2bfloat16_rn(v.x));
    float h1 = __bfloat162float(__float2bfloat16_rn(v.y));
    float h2 = __bfloat162float(__float2bfloat16_rn(v.z));
    float h3 = __bfloat162float(__float2bfloat16_rn(v.w));
    uint2 hw = make_uint2(pack_bf2(v.x, v.y), pack_bf2(v.z, v.w));
    uint2 lw = make_uint2(pack_bf2(v.x - h0, v.y - h1), pack_bf2(v.z - h2, v.w - h3));
    ((uint2*)g_Xh)[(size_t)gr * 256 + t] = hw;
    ((uint2*)g_Xl)[(size_t)gr * 256 + t] = lw;

    // zero-fill structurally-zero output rows
    const size_t nz4 = (size_t)B_ * Q0_ * D_ / 4;
    const size_t stride = (size_t)B_ * XR_ * 256;
    const size_t perb = (size_t)Q0_ * D_;
    for (size_t i = (size_t)gr * 256 + t; i < nz4; i += stride) {
        size_t e = i * 4;
        size_t bb = e / perb, rr = e % perb;
        *(float4*)(out + bb * (size_t)T_ * D_ + rr) = make_float4(0.f, 0.f, 0.f, 0.f);
    }
}

// ---------------------------------------------------------------------------
__global__ __launch_bounds__(256) void prep_w(
    const float* __restrict__ Wq, const float* __restrict__ Wk,
    const float* __restrict__ Wv, const float* __restrict__ Wo)
{
    const int z = blockIdx.z;
    const float* __restrict__ W = (z == 0) ? Wq : (z == 1) ? Wk : (z == 2) ? Wv : Wo;
    __shared__ float tile[64][33];
    const int n0 = blockIdx.x * 32, k0 = blockIdx.y * 64;
    const int tx = threadIdx.x, ty = threadIdx.y;

    #pragma unroll
    for (int rr = 0; rr < 8; rr++) {
        int kk = ty + rr * 8;
        tile[kk][tx] = W[(size_t)(k0 + kk) * D_ + n0 + tx];
    }
    __syncthreads();
    #pragma unroll
    for (int rr = 0; rr < 4; rr++) {
        int n = ty + rr * 8;
        float v0 = tile[tx * 2][n], v1 = tile[tx * 2 + 1][n];
        float h0 = __bfloat162float(__float2bfloat16_rn(v0));
        float h1 = __bfloat162float(__float2bfloat16_rn(v1));
        size_t base = (size_t)z * D_ * D_ + (size_t)(n0 + n) * D_ + k0;
        ((uint32_t*)(g_Wth + base))[tx] = pack_bf2(v0, v1);
        ((uint32_t*)(g_Wtl + base))[tx] = pack_bf2(v0 - h0, v1 - h1);
    }
}

// ---------------------------------------------------------------------------
// Tensor-core GEMM. modes 0/1/2 -> Q/K/V bf16 hi/lo; mode 3 -> final out.
// v2 mainloop: mt-pair MMA schedule (RAW distance 8), B-frags via ldsm4.
// ---------------------------------------------------------------------------
#define GM 128
#define GN 128
#define KC 32
#define SPAD 40
#define NCHUNK (D_/KC)
#define STG  (GM*SPAD)
#define STGB (STG*2)
#define GSMEM (8*STG*2)               // 81920 bytes

__global__ __launch_bounds__(256, 2) void gemm_mma(int mode_base, float* __restrict__ outF) {
    extern __shared__ __nv_bfloat16 ds[];
    __nv_bfloat16* sAh = ds;
    __nv_bfloat16* sAl = ds + 2 * STG;
    __nv_bfloat16* sBh = ds + 4 * STG;
    __nv_bfloat16* sBl = ds + 6 * STG;

    const int mode = mode_base + blockIdx.z;
    const int n0 = blockIdx.x * GN;
    const int m0 = blockIdx.y * GM;
    const int tid = threadIdx.x;
    const int wid = tid >> 5, lane = tid & 31;
    const int warp_m = (wid & 1) * 64;
    const int warp_n = (wid >> 1) * 32;

    const __nv_bfloat16* __restrict__ Bh_g = g_Wth + (size_t)mode * D_ * D_;
    const __nv_bfloat16* __restrict__ Bl_g = g_Wtl + (size_t)mode * D_ * D_;
    const __nv_bfloat16* __restrict__ Ah_g = (mode < 3) ? g_Xh : g_AOh;
    const __nv_bfloat16* __restrict__ Al_g = (mode < 3) ? g_Xl : g_AOl;

    const int ar0 = tid >> 2, ar1 = ar0 + 64;
    const int q = tid & 3;
    long asrc0 = -1, asrc1 = -1;
    {
        int m = m0 + ar0;
        if (m < MTOT_) {
            if (mode < 3) { int b = m / CTX_, i = m % CTX_; asrc0 = (long)b * XR_ + ((mode == 0) ? (NS_ + i) : ((i < NS_) ? i : (NS_ + i))); }
            else asrc0 = m;
        }
        m = m0 + ar1;
        if (m < MTOT_) {
            if (mode < 3) { int b = m / CTX_, i = m % CTX_; asrc1 = (long)b * XR_ + ((mode == 0) ? (NS_ + i) : ((i < NS_) ? i : (NS_ + i))); }
            else asrc1 = m;
        }
    }
    const int so0 = ar0 * SPAD + q * 8;
    const int so1 = ar1 * SPAD + q * 8;
    const uint32_t dAh0 = smem_u32(sAh + so0), dAh1 = smem_u32(sAh + so1);
    const uint32_t dAl0 = smem_u32(sAl + so0), dAl1 = smem_u32(sAl + so1);
    const uint32_t dBh0 = smem_u32(sBh + so0), dBh1 = smem_u32(sBh + so1);
    const uint32_t dBl0 = smem_u32(sBl + so0), dBl1 = smem_u32(sBl + so1);

    // A-frag ldsm addresses (per mt)
    const int a_row = (lane & 15), a_kh = (lane >> 4) << 3;
    uint32_t aAh[4], aAl[4];
    #pragma unroll
    for (int mt = 0; mt < 4; mt++) {
        int r = warp_m + mt * 16 + a_row;
        aAh[mt] = smem_u32(sAh + r * SPAD + a_kh);
        aAl[mt] = smem_u32(sAl + r * SPAD + a_kh);
    }
    // B-frag ldsm4 addresses: lanes 0-7 tile(nt,k0), 8-15 tile(nt,k1),
    // 16-23 tile(nt+1,k0), 24-31 tile(nt+1,k1)
    const int b_row = (lane & 7) + ((lane >> 4) & 1) * 8;
    const int b_k   = ((lane >> 3) & 1) * 8;
    uint32_t bB01h, bB01l, bB23h, bB23l;
    {
        int r01 = warp_n + b_row, r23 = warp_n + 16 + b_row;
        bB01h = smem_u32(sBh + r01 * SPAD + b_k);
        bB01l = smem_u32(sBl + r01 * SPAD + b_k);
        bB23h = smem_u32(sBh + r23 * SPAD + b_k);
        bB23l = smem_u32(sBl + r23 * SPAD + b_k);
    }

    float acc[4][4][4];
    #pragma unroll
    for (int a = 0; a < 4; a++)
        #pragma unroll
        for (int b = 0; b < 4; b++)
            #pragma unroll
            for (int cc = 0; cc < 4; cc++) acc[a][b][cc] = 0.f;

    auto issue = [&](int c) {
        const uint32_t so = (uint32_t)(c & 1) * STGB;
        const size_t koff = (size_t)c * KC + q * 8;
        const size_t a0 = (asrc0 >= 0 ? (size_t)asrc0 : 0) * D_ + koff;
        const size_t a1 = (asrc1 >= 0 ? (size_t)asrc1 : 0) * D_ + koff;
        cpa16(dAh0 + so, Ah_g + a0, asrc0 >= 0);
        cpa16(dAh1 + so, Ah_g + a1, asrc1 >= 0);
        cpa16(dAl0 + so, Al_g + a0, asrc0 >= 0);
        cpa16(dAl1 + so, Al_g + a1, asrc1 >= 0);
        cpa16(dBh0 + so, Bh_g + (size_t)(n0 + ar0) * D_ + koff, true);
        cpa16(dBh1 + so, Bh_g + (size_t)(n0 + ar1) * D_ + koff, true);
        cpa16(dBl0 + so, Bl_g + (size_t)(n0 + ar0) * D_ + koff, true);
        cpa16(dBl1 + so, Bl_g + (size_t)(n0 + ar1) * D_ + koff, true);
        CPA_COMMIT();
    };

    issue(0);
    issue(1);
    for (int c = 0; c < NCHUNK; c++) {
        if (c == NCHUNK - 1) { CPA_WAIT(0); } else { CPA_WAIT(1); }
        __syncthreads();
        const uint32_t so = (uint32_t)(c & 1) * STGB;
        #pragma unroll
        for (int ks = 0; ks < KC * 2; ks += 32) {
            uint32_t fBh[4][2], fBl[4][2], t4[4];
            ldsm4(t4, bB01h + so + ks);
            fBh[0][0] = t4[0]; fBh[0][1] = t4[1]; fBh[1][0] = t4[2]; fBh[1][1] = t4[3];
            ldsm4(t4, bB23h + so + ks);
            fBh[2][0] = t4[0]; fBh[2][1] = t4[1]; fBh[3][0] = t4[2]; fBh[3][1] = t4[3];
            ldsm4(t4, bB01l + so + ks);
            fBl[0][0] = t4[0]; fBl[0][1] = t4[1]; fBl[1][0] = t4[2]; fBl[1][1] = t4[3];
            ldsm4(t4, bB23l + so + ks);
            fBl[2][0] = t4[0]; fBl[2][1] = t4[1]; fBl[3][0] = t4[2]; fBl[3][1] = t4[3];

            #pragma unroll
            for (int mp = 0; mp < 2; mp++) {
                const int mt0 = mp * 2, mt1 = mp * 2 + 1;
                uint32_t fA0[4], fA1[4];
                ldsm4(fA0, aAh[mt0] + so + ks);
                ldsm4(fA1, aAh[mt1] + so + ks);
                #pragma unroll
                for (int nt = 0; nt < 4; nt++) mma16816(acc[mt0][nt], fA0, fBh[nt]);
                #pragma unroll
                for (int nt = 0; nt < 4; nt++) mma16816(acc[mt1][nt], fA1, fBh[nt]);
                #pragma unroll
                for (int nt = 0; nt < 4; nt++) mma16816(acc[mt0][nt], fA0, fBl[nt]);
                #pragma unroll
                for (int nt = 0; nt < 4; nt++) mma16816(acc[mt1][nt], fA1, fBl[nt]);
                ldsm4(fA0, aAl[mt0] + so + ks);
                ldsm4(fA1, aAl[mt1] + so + ks);
                #pragma unroll
                for (int nt = 0; nt < 4; nt++) mma16816(acc[mt0][nt], fA0, fBh[nt]);
                #pragma unroll
                for (int nt = 0; nt < 4; nt++) mma16816(acc[mt1][nt], fA1, fBh[nt]);
            }
        }
        __syncthreads();
        if (c + 2 < NCHUNK) issue(c + 2);
    }

    const int er = lane >> 2, ec = (lane & 3) * 2;
    if (mode < 3) {
        __nv_bfloat16* dh = (mode == 0) ? g_Qh : (mode == 1) ? g_Kh : g_Vh;
        __nv_bfloat16* dl = (mode == 0) ? g_Ql : (mode == 1) ? g_Kl : g_Vl;
        const float scl = (mode == 0) ? 0.125f : 1.0f;
        #pragma unroll
        for (int mt = 0; mt < 4; mt++) {
            #pragma unroll
            for (int half = 0; half < 2; half++) {
                int mm = m0 + warp_m + mt * 16 + er + half * 8;
                if (mm < MTOT_) {
                    size_t base = (size_t)mm * D_ + n0 + warp_n + ec;
                    #pragma unroll
                    for (int nt = 0; nt < 4; nt++) {
                        float v0 = acc[mt][nt][half * 2] * scl;
                        float v1 = acc[mt][nt][half * 2 + 1] * scl;
                        float t0 = __bfloat162float(__float2bfloat16_rn(v0));
                        float t1 = __bfloat162float(__float2bfloat16_rn(v1));
                        *(uint32_t*)(dh + base + nt * 8) = pack_bf2(v0, v1);
                        *(uint32_t*)(dl + base + nt * 8) = pack_bf2(v0 - t0, v1 - t1);
                    }
                }
            }
        }
    } else {
        #pragma unroll
        for (int mt = 0; mt < 4; mt++) {
            #pragma unroll
            for (int half = 0; half < 2; half++) {
                int mm = m0 + warp_m + mt * 16 + er + half * 8;
                if (mm < MTOT_) {
                    int b = mm / CTX_, i = mm % CTX_;
                    float* dst = outF + (size_t)(b * T_ + Q0_ + i) * D_ + n0;
                    #pragma unroll
                    for (int nt = 0; nt < 4; nt++) {
                        float2 v = make_float2(acc[mt][nt][half * 2], acc[mt][nt][half * 2 + 1]);
                        *(float2*)(dst + warp_n + nt * 8 + ec) = v;
                    }
                }
            }
        }
    }
}

// ---------------------------------------------------------------------------
// Flash attention on mma.sync (bf16 hi/lo). (R10, unchanged — it works.)
// ---------------------------------------------------------------------------
#define SST 72

__global__ __launch_bounds__(128) void attn_mma() {
    const int b = blockIdx.z, h = blockIdx.y, tau = blockIdx.x;
    const int tid = threadIdx.x, warp = tid >> 5, lane = tid & 31;

    __shared__ __nv_bfloat16 sKh[64 * SST], sKl[64 * SST];
    __shared__ __nv_bfloat16 sVh[64 * SST], sVl[64 * SST];

    const int gq0 = tau * 64 + warp * 16 + (lane >> 2);
    const int gq1 = gq0 + 8;

    const uint4 zv = make_uint4(0, 0, 0, 0);
    for (int it = tid; it < 64 * 8; it += 128) {
        int row = it >> 3, dd = (it & 7) * 8;
        int gq = tau * 64 + row;
        uint4 vh = zv, vl = zv;
        if (gq < CTX_) {
            size_t off = (size_t)(b * CTX_ + gq) * D_ + h * DH_ + dd;
            vh = *(const uint4*)(g_Qh + off);
            vl = *(const uint4*)(g_Ql + off);
        }
        *(uint4*)(sKh + row * SST + dd) = vh;
        *(uint4*)(sKl + row * SST + dd) = vl;
    }
    __syncthreads();

    uint32_t QhF[4][4], QlF[4][4];
    {
        const uint32_t qoff = (uint32_t)((warp * 16 + (lane & 15)) * (SST * 2) + ((lane >> 4) & 1) * 16);
        const uint32_t bh = smem_u32(sKh) + qoff;
        const uint32_t bl = smem_u32(sKl) + qoff;
        #pragma unroll
        for (int ks = 0; ks < 4; ks++) {
            ldsm4(QhF[ks], bh + ks * 32);
            ldsm4(QlF[ks], bl + ks * 32);
        }
    }

    float oacc[8][4];
    #pragma unroll
    for (int nt = 0; nt < 8; nt++)
        #pragma unroll
        for (int c = 0; c < 4; c++) oacc[nt][c] = 0.f;
    float m0 = -1e30f, m1 = -1e30f, l0 = 0.f, l1 = 0.f;

    const uint32_t kfo = (uint32_t)((lane & 7) * (SST * 2) + ((lane >> 3) & 1) * 16);
    const uint32_t kbh = smem_u32(sKh) + kfo;
    const uint32_t kbl = smem_u32(sKl) + kfo;
    const uint32_t vfo = (uint32_t)(((lane & 7) + ((lane >> 3) & 1) * 8) * (SST * 2));
    const uint32_t vbh = smem_u32(sVh) + vfo;
    const uint32_t vbl = smem_u32(sVl) + vfo;

    for (int t = 0; t <= tau; t++) {
        __syncthreads();
        for (int it = tid; it < 64 * 8; it += 128) {
            int row = it >> 3, dd = (it & 7) * 8;
            int j = t * 64 + row;
            uint4 kh = zv, kl = zv, vh = zv, vl = zv;
            if (j < CTX_) {
                size_t off = (size_t)(b * CTX_ + j) * D_ + h * DH_ + dd;
                kh = *(const uint4*)(g_Kh + off);
                kl = *(const uint4*)(g_Kl + off);
                vh = *(const uint4*)(g_Vh + off);
                vl = *(const uint4*)(g_Vl + off);
            }
            *(uint4*)(sKh + row * SST + dd) = kh;
            *(uint4*)(sKl + row * SST + dd) = kl;
            *(uint4*)(sVh + row * SST + dd) = vh;
            *(uint4*)(sVl + row * SST + dd) = vl;
        }
        __syncthreads();

        float sacc[8][4];
        #pragma unroll
        for (int nt = 0; nt < 8; nt++)
            #pragma unroll
            for (int c = 0; c < 4; c++) sacc[nt][c] = 0.f;

        #pragma unroll
        for (int ks = 0; ks < 4; ks++) {
            #pragma unroll
            for (int nt = 0; nt < 8; nt++) {
                uint32_t fbh[2], fbl[2];
                ldsm2(fbh, kbh + (uint32_t)(nt * 8 * SST * 2 + ks * 32));
                ldsm2(fbl, kbl + (uint32_t)(nt * 8 * SST * 2 + ks * 32));
                mma16816(sacc[nt], QhF[ks], fbh);
                mma16816(sacc[nt], QhF[ks], fbl);
                mma16816(sacc[nt], QlF[ks], fbh);
            }
        }

        if (t == tau) {
            const int cbase = t * 64 + 2 * (lane & 3);
            #pragma unroll
            for (int nt = 0; nt < 8; nt++) {
                int c0 = cbase + nt * 8, c1 = c0 + 1;
                if (c0 > gq0) sacc[nt][0] = -1e30f;
                if (c1 > gq0) sacc[nt][1] = -1e30f;
                if (c0 > gq1) sacc[nt][2] = -1e30f;
                if (c1 > gq1) sacc[nt][3] = -1e30f;
            }
        }

        float mx0 = -1e30f, mx1 = -1e30f;
        #pragma unroll
        for (int nt = 0; nt < 8; nt++) {
            mx0 = fmaxf(mx0, fmaxf(sacc[nt][0], sacc[nt][1]));
            mx1 = fmaxf(mx1, fmaxf(sacc[nt][2], sacc[nt][3]));
        }
        mx0 = fmaxf(mx0, __shfl_xor_sync(0xFFFFFFFFu, mx0, 1));
        mx0 = fmaxf(mx0, __shfl_xor_sync(0xFFFFFFFFu, mx0, 2));
        mx1 = fmaxf(mx1, __shfl_xor_sync(0xFFFFFFFFu, mx1, 1));
        mx1 = fmaxf(mx1, __shfl_xor_sync(0xFFFFFFFFu, mx1, 2));
        float mn0 = fmaxf(m0, mx0), mn1 = fmaxf(m1, mx1);
        float al0 = __expf(m0 - mn0), al1 = __expf(m1 - mn1);
        m0 = mn0; m1 = mn1;

        float rs0 = 0.f, rs1 = 0.f;
        #pragma unroll
        for (int nt = 0; nt < 8; nt++) {
            float p00 = __expf(sacc[nt][0] - mn0);
            float p01 = __expf(sacc[nt][1] - mn0);
            float p10 = __expf(sacc[nt][2] - mn1);
            float p11 = __expf(sacc[nt][3] - mn1);
            sacc[nt][0] = p00; sacc[nt][1] = p01;
            sacc[nt][2] = p10; sacc[nt][3] = p11;
            rs0 += p00 + p01; rs1 += p10 + p11;
        }
        rs0 += __shfl_xor_sync(0xFFFFFFFFu, rs0, 1);
        rs0 += __shfl_xor_sync(0xFFFFFFFFu, rs0, 2);
        rs1 += __shfl_xor_sync(0xFFFFFFFFu, rs1, 1);
        rs1 += __shfl_xor_sync(0xFFFFFFFFu, rs1, 2);
        l0 = l0 * al0 + rs0;
        l1 = l1 * al1 + rs1;

        #pragma unroll
        for (int nt = 0; nt < 8; nt++) {
            oacc[nt][0] *= al0; oacc[nt][1] *= al0;
            oacc[nt][2] *= al1; oacc[nt][3] *= al1;
        }

        #pragma unroll
        for (int u = 0; u < 4; u++) {
            uint32_t Ph[4], Pl[4];
            #pragma unroll
            for (int half = 0; half < 2; half++) {
                const float* pa = sacc[2 * u + half];
                float h0 = __bfloat162float(__float2bfloat16_rn(pa[0]));
                float h1 = __bfloat162float(__float2bfloat16_rn(pa[1]));
                float h2 = __bfloat162float(__float2bfloat16_rn(pa[2]));
                float h3 = __bfloat162float(__float2bfloat16_rn(pa[3]));
                Ph[half * 2 + 0] = pack_bf2(pa[0], pa[1]);
                Ph[half * 2 + 1] = pack_bf2(pa[2], pa[3]);
                Pl[half * 2 + 0] = pack_bf2(pa[0] - h0, pa[1] - h1);
                Pl[half * 2 + 1] = pack_bf2(pa[2] - h2, pa[3] - h3);
            }
            #pragma unroll
            for (int nt = 0; nt < 8; nt++) {
                uint32_t fvh[2], fvl[2];
                ldsm2t(fvh, vbh + (uint32_t)(u * 16 * SST * 2 + nt * 16));
                ldsm2t(fvl, vbl + (uint32_t)(u * 16 * SST * 2 + nt * 16));
                mma16816(oacc[nt], Ph, fvh);
                mma16816(oacc[nt], Ph, fvl);
                mma16816(oacc[nt], Pl, fvh);
            }
        }
    }

    const int ccol = 2 * (lane & 3);
    if (gq0 < CTX_) {
        float inv = 1.f / l0;
        size_t base = (size_t)(b * CTX_ + gq0) * D_ + h * DH_ + ccol;
        #pragma unroll
        for (int nt = 0; nt < 8; nt++) {
            float v0 = oacc[nt][0] * inv, v1 = oacc[nt][1] * inv;
            float t0 = __bfloat162float(__float2bfloat16_rn(v0));
            float t1 = __bfloat162float(__float2bfloat16_rn(v1));
            *(uint32_t*)(g_AOh + base + nt * 8) = pack_bf2(v0, v1);
            *(uint32_t*)(g_AOl + base + nt * 8) = pack_bf2(v0 - t0, v1 - t1);
        }
    }
    if (gq1 < CTX_) {
        float inv = 1.f / l1;
        size_t base = (size_t)(b * CTX_ + gq1) * D_ + h * DH_ + ccol;
        #pragma unroll
        for (int nt = 0; nt < 8; nt++) {
            float v0 = oacc[nt][2] * inv, v1 = oacc[nt][3] * inv;
            float t0 = __bfloat162float(__float2bfloat16_rn(v0));
            float t1 = __bfloat162float(__float2bfloat16_rn(v1));
            *(uint32_t*)(g_AOh + base + nt * 8) = pack_bf2(v0, v1);
            *(uint32_t*)(g_AOl + base + nt * 8) = pack_bf2(v0 - t0, v1 - t1);
        }
    }
}

// ---------------------------------------------------------------------------
extern "C" void kernel_launch(void* const* d_in, const int* in_sizes, int n_in,
                              void* d_out, int out_size) {
    const float* x  = (const float*)d_in[0];
    const float* Wq = (const float*)d_in[1];
    const float* Wk = (const float*)d_in[2];
    const float* Wv = (const float*)d_in[3];
    const float* Wo = (const float*)d_in[4];
    float* out = (float*)d_out;

    cudaFuncSetAttribute(gemm_mma, cudaFuncAttributeMaxDynamicSharedMemorySize, GSMEM);

    // 1. Prep (gather+split x, zero-fill dead rows) + weight transpose/split
    prep_x<<<B_ * XR_, 256>>>(x, out);
    prep_w<<<dim3(D_ / 32, D_ / 64, 4), dim3(32, 8)>>>(Wq, Wk, Wv, Wo);

    // 2. Q/K/V projections -> bf16 hi/lo (Q pre-scaled by 0.125)
    gemm_mma<<<dim3(D_ / GN, (MTOT_ + GM - 1) / GM, 3), 256, GSMEM>>>(0, nullptr);

    // 3. Flash attention on tensor cores
    attn_mma<<<dim3((CTX_ + 63) / 64, H_, B_), 128>>>();

    // 4. Output projection, scattered to live rows
    gemm_mma<<<dim3(D_ / GN, (MTOT_ + GM - 1) / GM, 1), 256, GSMEM>>>(3, out);
}

// round 13
// speedup vs baseline: 2.7396x; 1.0555x over previous
#include <cuda_runtime.h>
#include <cuda_bf16.h>
#include <cstdint>

#define B_    4
#define T_    4096
#define D_    1024
#define H_    16
#define DH_   64
#define NS_   4
#define CTX_  516
#define Q0_   3580
#define MTOT_ (B_*CTX_)   // 2064
#define XR_   520         // per-batch gathered x rows: 4 sinks + 516 window

// ---------------------------------------------------------------------------
// Device scratch (no allocation allowed)
// ---------------------------------------------------------------------------
__device__ __align__(16) __nv_bfloat16 g_Xh[B_*XR_*D_];
__device__ __align__(16) __nv_bfloat16 g_Xl[B_*XR_*D_];
__device__ __align__(16) __nv_bfloat16 g_Wth[4*D_*D_];   // W^T hi: [z][n][k]
__device__ __align__(16) __nv_bfloat16 g_Wtl[4*D_*D_];   // W^T lo
// Q/K/V in bf16 hi/lo (Q pre-scaled by 0.125)
__device__ __align__(16) __nv_bfloat16 g_Qh[MTOT_*D_];
__device__ __align__(16) __nv_bfloat16 g_Ql[MTOT_*D_];
__device__ __align__(16) __nv_bfloat16 g_Kh[MTOT_*D_];
__device__ __align__(16) __nv_bfloat16 g_Kl[MTOT_*D_];
__device__ __align__(16) __nv_bfloat16 g_Vh[MTOT_*D_];
__device__ __align__(16) __nv_bfloat16 g_Vl[MTOT_*D_];
__device__ __align__(16) __nv_bfloat16 g_AOh[MTOT_*D_];
__device__ __align__(16) __nv_bfloat16 g_AOl[MTOT_*D_];

// ---------------------------------------------------------------------------
__device__ __forceinline__ uint32_t smem_u32(const void* p) {
    uint32_t a;
    asm("{ .reg .u64 t; cvta.to.shared.u64 t, %1; cvt.u32.u64 %0, t; }" : "=r"(a) : "l"(p));
    return a;
}
__device__ __forceinline__ uint32_t pack_bf2(float a, float b) {
    return ((uint32_t)__bfloat16_as_ushort(__float2bfloat16_rn(b)) << 16) |
           (uint32_t)__bfloat16_as_ushort(__float2bfloat16_rn(a));
}
__device__ __forceinline__ void ldsm4(uint32_t* r, uint32_t addr) {
    asm volatile("ldmatrix.sync.aligned.m8n8.x4.shared.b16 {%0,%1,%2,%3}, [%4];"
        : "=r"(r[0]), "=r"(r[1]), "=r"(r[2]), "=r"(r[3]) : "r"(addr));
}
__device__ __forceinline__ void ldsm4t(uint32_t* r, uint32_t addr) {
    asm volatile("ldmatrix.sync.aligned.m8n8.x4.trans.shared.b16 {%0,%1,%2,%3}, [%4];"
        : "=r"(r[0]), "=r"(r[1]), "=r"(r[2]), "=r"(r[3]) : "r"(addr));
}
__device__ __forceinline__ void mma16816(float* c, const uint32_t* a, const uint32_t* b) {
    asm volatile(
        "mma.sync.aligned.m16n8k16.row.col.f32.bf16.bf16.f32 "
        "{%0,%1,%2,%3}, {%4,%5,%6,%7}, {%8,%9}, {%0,%1,%2,%3};"
        : "+f"(c[0]), "+f"(c[1]), "+f"(c[2]), "+f"(c[3])
        : "r"(a[0]), "r"(a[1]), "r"(a[2]), "r"(a[3]), "r"(b[0]), "r"(b[1]));
}
__device__ __forceinline__ void cpa16(uint32_t dst, const void* src, bool valid) {
    int sz = valid ? 16 : 0;
    asm volatile("cp.async.cg.shared.global [%0], [%1], 16, %2;"
        :: "r"(dst), "l"(src), "r"(sz) : "memory");
}
#define CPA_COMMIT() asm volatile("cp.async.commit_group;" ::: "memory")
#define CPA_WAIT(n)  asm volatile("cp.async.wait_group %0;" :: "n"(n) : "memory")

// ---------------------------------------------------------------------------
// prep_x: gather live x rows, split fp32 -> bf16 hi/lo; zero-fill dead rows.
// ---------------------------------------------------------------------------
__global__ __launch_bounds__(256) void prep_x(const float* __restrict__ x,
                                              float* __restrict__ out) {
    int gr = blockIdx.x;
    int b = gr / XR_, r = gr % XR_;
    int tok = (r < NS_) ? r : (Q0_ + (r - NS_));
    int t = threadIdx.x;
    float4 v = *(const float4*)(x + (size_t)(b * T_ + tok) * D_ + t * 4);
    float h0 = __bfloat162float(__float2bfloat16_rn(v.x));
    float h1 = __bfloat162float(__float2bfloat16_rn(v.y));
    float h2 = __bfloat162float(__float2bfloat16_rn(v.z));
    float h3 = __bfloat162float(__float2bfloat16_rn(v.w));
    uint2 hw = make_uint2(pack_bf2(v.x, v.y), pack_bf2(v.z, v.w));
    uint2 lw = make_uint2(pack_bf2(v.x - h0, v.y - h1), pack_bf2(v.z - h2, v.w - h3));
    ((uint2*)g_Xh)[(size_t)gr * 256 + t] = hw;
    ((uint2*)g_Xl)[(size_t)gr * 256 + t] = lw;

    const size_t nz4 = (size_t)B_ * Q0_ * D_ / 4;
    const size_t stride = (size_t)B_ * XR_ * 256;
    const size_t perb = (size_t)Q0_ * D_;
    for (size_t i = (size_t)gr * 256 + t; i < nz4; i += stride) {
        size_t e = i * 4;
        size_t bb = e / perb, rr = e % perb;
        *(float4*)(out + bb * (size_t)T_ * D_ + rr) = make_float4(0.f, 0.f, 0.f, 0.f);
    }
}

// ---------------------------------------------------------------------------
__global__ __launch_bounds__(256) void prep_w(
    const float* __restrict__ Wq, const float* __restrict__ Wk,
    const float* __restrict__ Wv, const float* __restrict__ Wo)
{
    const int z = blockIdx.z;
    const float* __restrict__ W = (z == 0) ? Wq : (z == 1) ? Wk : (z == 2) ? Wv : Wo;
    __shared__ float tile[64][33];
    const int n0 = blockIdx.x * 32, k0 = blockIdx.y * 64;
    const int tx = threadIdx.x, ty = threadIdx.y;

    #pragma unroll
    for (int rr = 0; rr < 8; rr++) {
        int kk = ty + rr * 8;
        tile[kk][tx] = W[(size_t)(k0 + kk) * D_ + n0 + tx];
    }
    __syncthreads();
    #pragma unroll
    for (int rr = 0; rr < 4; rr++) {
        int n = ty + rr * 8;
        float v0 = tile[tx * 2][n], v1 = tile[tx * 2 + 1][n];
        float h0 = __bfloat162float(__float2bfloat16_rn(v0));
        float h1 = __bfloat162float(__float2bfloat16_rn(v1));
        size_t base = (size_t)z * D_ * D_ + (size_t)(n0 + n) * D_ + k0;
        ((uint32_t*)(g_Wth + base))[tx] = pack_bf2(v0, v1);
        ((uint32_t*)(g_Wtl + base))[tx] = pack_bf2(v0 - h0, v1 - h1);
    }
}

// ---------------------------------------------------------------------------
// Tensor-core GEMM (R11 engine, unchanged).
// ---------------------------------------------------------------------------
#define GM 128
#define GN 128
#define KC 32
#define SPAD 40
#define NCHUNK (D_/KC)
#define STG  (GM*SPAD)
#define STGB (STG*2)
#define GSMEM (8*STG*2)               // 81920 bytes

__global__ __launch_bounds__(256, 2) void gemm_mma(int mode_base, float* __restrict__ outF) {
    extern __shared__ __nv_bfloat16 ds[];
    __nv_bfloat16* sAh = ds;
    __nv_bfloat16* sAl = ds + 2 * STG;
    __nv_bfloat16* sBh = ds + 4 * STG;
    __nv_bfloat16* sBl = ds + 6 * STG;

    const int mode = mode_base + blockIdx.z;
    const int n0 = blockIdx.x * GN;
    const int m0 = blockIdx.y * GM;
    const int tid = threadIdx.x;
    const int wid = tid >> 5, lane = tid & 31;
    const int warp_m = (wid & 1) * 64;
    const int warp_n = (wid >> 1) * 32;

    const __nv_bfloat16* __restrict__ Bh_g = g_Wth + (size_t)mode * D_ * D_;
    const __nv_bfloat16* __restrict__ Bl_g = g_Wtl + (size_t)mode * D_ * D_;
    const __nv_bfloat16* __restrict__ Ah_g = (mode < 3) ? g_Xh : g_AOh;
    const __nv_bfloat16* __restrict__ Al_g = (mode < 3) ? g_Xl : g_AOl;

    const int ar0 = tid >> 2, ar1 = ar0 + 64;
    const int q = tid & 3;
    long asrc0 = -1, asrc1 = -1;
    {
        int m = m0 + ar0;
        if (m < MTOT_) {
            if (mode < 3) { int b = m / CTX_, i = m % CTX_; asrc0 = (long)b * XR_ + ((mode == 0) ? (NS_ + i) : ((i < NS_) ? i : (NS_ + i))); }
            else asrc0 = m;
        }
        m = m0 + ar1;
        if (m < MTOT_) {
            if (mode < 3) { int b = m / CTX_, i = m % CTX_; asrc1 = (long)b * XR_ + ((mode == 0) ? (NS_ + i) : ((i < NS_) ? i : (NS_ + i))); }
            else asrc1 = m;
        }
    }
    const int so0 = ar0 * SPAD + q * 8;
    const int so1 = ar1 * SPAD + q * 8;
    const uint32_t dAh0 = smem_u32(sAh + so0), dAh1 = smem_u32(sAh + so1);
    const uint32_t dAl0 = smem_u32(sAl + so0), dAl1 = smem_u32(sAl + so1);
    const uint32_t dBh0 = smem_u32(sBh + so0), dBh1 = smem_u32(sBh + so1);
    const uint32_t dBl0 = smem_u32(sBl + so0), dBl1 = smem_u32(sBl + so1);

    const int a_row = (lane & 15), a_kh = (lane >> 4) << 3;
    uint32_t aAh[4], aAl[4];
    #pragma unroll
    for (int mt = 0; mt < 4; mt++) {
        int r = warp_m + mt * 16 + a_row;
        aAh[mt] = smem_u32(sAh + r * SPAD + a_kh);
        aAl[mt] = smem_u32(sAl + r * SPAD + a_kh);
    }
    const int b_row = (lane & 7) + ((lane >> 4) & 1) * 8;
    const int b_k   = ((lane >> 3) & 1) * 8;
    uint32_t bB01h, bB01l, bB23h, bB23l;
    {
        int r01 = warp_n + b_row, r23 = warp_n + 16 + b_row;
        bB01h = smem_u32(sBh + r01 * SPAD + b_k);
        bB01l = smem_u32(sBl + r01 * SPAD + b_k);
        bB23h = smem_u32(sBh + r23 * SPAD + b_k);
        bB23l = smem_u32(sBl + r23 * SPAD + b_k);
    }

    float acc[4][4][4];
    #pragma unroll
    for (int a = 0; a < 4; a++)
        #pragma unroll
        for (int b = 0; b < 4; b++)
            #pragma unroll
            for (int cc = 0; cc < 4; cc++) acc[a][b][cc] = 0.f;

    auto issue = [&](int c) {
        const uint32_t so = (uint32_t)(c & 1) * STGB;
        const size_t koff = (size_t)c * KC + q * 8;
        const size_t a0 = (asrc0 >= 0 ? (size_t)asrc0 : 0) * D_ + koff;
        const size_t a1 = (asrc1 >= 0 ? (size_t)asrc1 : 0) * D_ + koff;
        cpa16(dAh0 + so, Ah_g + a0, asrc0 >= 0);
        cpa16(dAh1 + so, Ah_g + a1, asrc1 >= 0);
        cpa16(dAl0 + so, Al_g + a0, asrc0 >= 0);
        cpa16(dAl1 + so, Al_g + a1, asrc1 >= 0);
        cpa16(dBh0 + so, Bh_g + (size_t)(n0 + ar0) * D_ + koff, true);
        cpa16(dBh1 + so, Bh_g + (size_t)(n0 + ar1) * D_ + koff, true);
        cpa16(dBl0 + so, Bl_g + (size_t)(n0 + ar0) * D_ + koff, true);
        cpa16(dBl1 + so, Bl_g + (size_t)(n0 + ar1) * D_ + koff, true);
        CPA_COMMIT();
    };

    issue(0);
    issue(1);
    for (int c = 0; c < NCHUNK; c++) {
        if (c == NCHUNK - 1) { CPA_WAIT(0); } else { CPA_WAIT(1); }
        __syncthreads();
        const uint32_t so = (uint32_t)(c & 1) * STGB;
        #pragma unroll
        for (int ks = 0; ks < KC * 2; ks += 32) {
            uint32_t fBh[4][2], fBl[4][2], t4[4];
            ldsm4(t4, bB01h + so + ks);
            fBh[0][0] = t4[0]; fBh[0][1] = t4[1]; fBh[1][0] = t4[2]; fBh[1][1] = t4[3];
            ldsm4(t4, bB23h + so + ks);
            fBh[2][0] = t4[0]; fBh[2][1] = t4[1]; fBh[3][0] = t4[2]; fBh[3][1] = t4[3];
            ldsm4(t4, bB01l + so + ks);
            fBl[0][0] = t4[0]; fBl[0][1] = t4[1]; fBl[1][0] = t4[2]; fBl[1][1] = t4[3];
            ldsm4(t4, bB23l + so + ks);
            fBl[2][0] = t4[0]; fBl[2][1] = t4[1]; fBl[3][0] = t4[2]; fBl[3][1] = t4[3];

            #pragma unroll
            for (int mp = 0; mp < 2; mp++) {
                const int mt0 = mp * 2, mt1 = mp * 2 + 1;
                uint32_t fA0[4], fA1[4];
                ldsm4(fA0, aAh[mt0] + so + ks);
                ldsm4(fA1, aAh[mt1] + so + ks);
                #pragma unroll
                for (int nt = 0; nt < 4; nt++) mma16816(acc[mt0][nt], fA0, fBh[nt]);
                #pragma unroll
                for (int nt = 0; nt < 4; nt++) mma16816(acc[mt1][nt], fA1, fBh[nt]);
                #pragma unroll
                for (int nt = 0; nt < 4; nt++) mma16816(acc[mt0][nt], fA0, fBl[nt]);
                #pragma unroll
                for (int nt = 0; nt < 4; nt++) mma16816(acc[mt1][nt], fA1, fBl[nt]);
                ldsm4(fA0, aAl[mt0] + so + ks);
                ldsm4(fA1, aAl[mt1] + so + ks);
                #pragma unroll
                for (int nt = 0; nt < 4; nt++) mma16816(acc[mt0][nt], fA0, fBh[nt]);
                #pragma unroll
                for (int nt = 0; nt < 4; nt++) mma16816(acc[mt1][nt], fA1, fBh[nt]);
            }
        }
        __syncthreads();
        if (c + 2 < NCHUNK) issue(c + 2);
    }

    const int er = lane >> 2, ec = (lane & 3) * 2;
    if (mode < 3) {
        __nv_bfloat16* dh = (mode == 0) ? g_Qh : (mode == 1) ? g_Kh : g_Vh;
        __nv_bfloat16* dl = (mode == 0) ? g_Ql : (mode == 1) ? g_Kl : g_Vl;
        const float scl = (mode == 0) ? 0.125f : 1.0f;
        #pragma unroll
        for (int mt = 0; mt < 4; mt++) {
            #pragma unroll
            for (int half = 0; half < 2; half++) {
                int mm = m0 + warp_m + mt * 16 + er + half * 8;
                if (mm < MTOT_) {
                    size_t base = (size_t)mm * D_ + n0 + warp_n + ec;
                    #pragma unroll
                    for (int nt = 0; nt < 4; nt++) {
                        float v0 = acc[mt][nt][half * 2] * scl;
                        float v1 = acc[mt][nt][half * 2 + 1] * scl;
                        float t0 = __bfloat162float(__float2bfloat16_rn(v0));
                        float t1 = __bfloat162float(__float2bfloat16_rn(v1));
                        *(uint32_t*)(dh + base + nt * 8) = pack_bf2(v0, v1);
                        *(uint32_t*)(dl + base + nt * 8) = pack_bf2(v0 - t0, v1 - t1);
                    }
                }
            }
        }
    } else {
        #pragma unroll
        for (int mt = 0; mt < 4; mt++) {
            #pragma unroll
            for (int half = 0; half < 2; half++) {
                int mm = m0 + warp_m + mt * 16 + er + half * 8;
                if (mm < MTOT_) {
                    int b = mm / CTX_, i = mm % CTX_;
                    float* dst = outF + (size_t)(b * T_ + Q0_ + i) * D_ + n0;
                    #pragma unroll
                    for (int nt = 0; nt < 4; nt++) {
                        float2 v = make_float2(acc[mt][nt][half * 2], acc[mt][nt][half * 2 + 1]);
                        *(float2*)(dst + warp_n + nt * 8 + ec) = v;
                    }
                }
            }
        }
    }
}

// ---------------------------------------------------------------------------
// Flash attention v2: cp.async double-buffered K/V, ldsm4 frag loads,
// tile-paired blocks ({p, 8-p}) for load balance. 128 threads.
// ---------------------------------------------------------------------------
#define SST   72
#define TILEH (64*SST)                 // halves per array per stage
#define NTILE ((CTX_ + 63) / 64)       // 9
#define TMAX  (NTILE - 1)              // 8
#define NPAIR ((NTILE + 1) / 2)        // 5
#define ASMEM (2 * 4 * TILEH * 2)      // 73728 bytes

__global__ __launch_bounds__(128) void attn_mma() {
    extern __shared__ __nv_bfloat16 as_[];
    // stage s, array a: as_ + (s*4 + a)*TILEH ; a: 0=Kh 1=Kl 2=Vh 3=Vl
    const int b = blockIdx.z, h = blockIdx.y, p = blockIdx.x;
    const int tid = threadIdx.x, warp = tid >> 5, lane = tid & 31;

    const uint32_t sbase = smem_u32(as_);
    const __nv_bfloat16* __restrict__ KVsrc[4] = { g_Kh, g_Kl, g_Vh, g_Vl };

    // per-thread staging geometry (4 rows x 1 uint4 per array per iteration)
    const int srow = tid >> 3;          // 0..15 (x4 iters -> 64 rows)
    const int sdd  = (tid & 7) * 8;     // halves

    // frag lane maps
    const uint32_t k4o = (uint32_t)((((lane & 7) + ((lane >> 4) & 1) * 8) * SST + ((lane >> 3) & 1) * 8) * 2);
    const uint32_t v4o = (uint32_t)((((lane & 7) + ((lane >> 3) & 1) * 8) * SST) * 2 + ((lane >> 4) & 1) * 16);
    const uint32_t qfo = (uint32_t)((warp * 16 + (lane & 15)) * (SST * 2) + ((lane >> 4) & 1) * 16);

    const int npass = (2 * p == TMAX) ? 1 : 2;
    for (int pass = 0; pass < npass; pass++) {
        const int tau = (pass == 0) ? p : (TMAX - p);
        const int gq0 = tau * 64 + warp * 16 + (lane >> 2);
        const int gq1 = gq0 + 8;

        // ---- stage Q into stage0 Kh/Kl (direct, zero-filled), extract frags ----
        const uint4 zv = make_uint4(0, 0, 0, 0);
        for (int it = tid; it < 64 * 8; it += 128) {
            int row = it >> 3, dd = (it & 7) * 8;
            int gq = tau * 64 + row;
            uint4 vh = zv, vl = zv;
            if (gq < CTX_) {
                size_t off = (size_t)(b * CTX_ + gq) * D_ + h * DH_ + dd;
                vh = *(const uint4*)(g_Qh + off);
                vl = *(const uint4*)(g_Ql + off);
            }
            *(uint4*)(as_ + 0 * TILEH + row * SST + dd) = vh;
            *(uint4*)(as_ + 1 * TILEH + row * SST + dd) = vl;
        }
        __syncthreads();
        uint32_t QhF[4][4], QlF[4][4];
        #pragma unroll
        for (int ks = 0; ks < 4; ks++) {
            ldsm4(QhF[ks], sbase + 0 * TILEH * 2 + qfo + ks * 32);
            ldsm4(QlF[ks], sbase + 1 * TILEH * 2 + qfo + ks * 32);
        }
        __syncthreads();

        float oacc[8][4];
        #pragma unroll
        for (int nt = 0; nt < 8; nt++)
            #pragma unroll
            for (int c = 0; c < 4; c++) oacc[nt][c] = 0.f;
        float m0 = -1e30f, m1 = -1e30f, l0 = 0.f, l1 = 0.f;

        // ---- cp.async tile issue ----
        auto issueTile = [&](int t, int s) {
            #pragma unroll
            for (int rr = 0; rr < 4; rr++) {
                int row = srow + rr * 16;
                int j = t * 64 + row;
                bool v = (j < CTX_);
                size_t off = (size_t)(b * CTX_ + (v ? j : 0)) * D_ + h * DH_ + sdd;
                uint32_t dst = sbase + (uint32_t)(((s * 4) * TILEH + row * SST + sdd) * 2);
                #pragma unroll
                for (int a = 0; a < 4; a++)
                    cpa16(dst + (uint32_t)(a * TILEH * 2), KVsrc[a] + off, v);
            }
            CPA_COMMIT();
        };

        issueTile(0, 0);
        for (int t = 0; t <= tau; t++) {
            if (t + 1 <= tau) { issueTile(t + 1, (t + 1) & 1); CPA_WAIT(1); }
            else              { CPA_WAIT(0); }
            __syncthreads();
            const uint32_t sb = sbase + (uint32_t)((t & 1) * 4 * TILEH * 2);
            const uint32_t kbh = sb + 0 * TILEH * 2 + k4o;
            const uint32_t kbl = sb + 1 * TILEH * 2 + k4o;
            const uint32_t vbh = sb + 2 * TILEH * 2 + v4o;
            const uint32_t vbl = sb + 3 * TILEH * 2 + v4o;

            // ---- S = Q K^T ----
            float sacc[8][4];
            #pragma unroll
            for (int nt = 0; nt < 8; nt++)
                #pragma unroll
                for (int c = 0; c < 4; c++) sacc[nt][c] = 0.f;

            #pragma unroll
            for (int ks = 0; ks < 4; ks++) {
                #pragma unroll
                for (int pp = 0; pp < 4; pp++) {
                    uint32_t th[4], tl[4];
                    ldsm4(th, kbh + (uint32_t)(pp * 16 * SST * 2 + ks * 32));
                    ldsm4(tl, kbl + (uint32_t)(pp * 16 * SST * 2 + ks * 32));
                    mma16816(sacc[2 * pp + 0], QhF[ks], th);
                    mma16816(sacc[2 * pp + 1], QhF[ks], th + 2);
                    mma16816(sacc[2 * pp + 0], QhF[ks], tl);
                    mma16816(sacc[2 * pp + 1], QhF[ks], tl + 2);
                    mma16816(sacc[2 * pp + 0], QlF[ks], th);
                    mma16816(sacc[2 * pp + 1], QlF[ks], th + 2);
                }
            }

            // ---- causal mask (diagonal tile only) ----
            if (t == tau) {
                const int cbase = t * 64 + 2 * (lane & 3);
                #pragma unroll
                for (int nt = 0; nt < 8; nt++) {
                    int c0 = cbase + nt * 8, c1 = c0 + 1;
                    if (c0 > gq0) sacc[nt][0] = -1e30f;
                    if (c1 > gq0) sacc[nt][1] = -1e30f;
                    if (c0 > gq1) sacc[nt][2] = -1e30f;
                    if (c1 > gq1) sacc[nt][3] = -1e30f;
                }
            }

            // ---- online softmax ----
            float mx0 = -1e30f, mx1 = -1e30f;
            #pragma unroll
            for (int nt = 0; nt < 8; nt++) {
                mx0 = fmaxf(mx0, fmaxf(sacc[nt][0], sacc[nt][1]));
                mx1 = fmaxf(mx1, fmaxf(sacc[nt][2], sacc[nt][3]));
            }
            mx0 = fmaxf(mx0, __shfl_xor_sync(0xFFFFFFFFu, mx0, 1));
            mx0 = fmaxf(mx0, __shfl_xor_sync(0xFFFFFFFFu, mx0, 2));
            mx1 = fmaxf(mx1, __shfl_xor_sync(0xFFFFFFFFu, mx1, 1));
            mx1 = fmaxf(mx1, __shfl_xor_sync(0xFFFFFFFFu, mx1, 2));
            float mn0 = fmaxf(m0, mx0), mn1 = fmaxf(m1, mx1);
            float al0 = __expf(m0 - mn0), al1 = __expf(m1 - mn1);
            m0 = mn0; m1 = mn1;

            float rs0 = 0.f, rs1 = 0.f;
            #pragma unroll
            for (int nt = 0; nt < 8; nt++) {
                float p00 = __expf(sacc[nt][0] - mn0);
                float p01 = __expf(sacc[nt][1] - mn0);
                float p10 = __expf(sacc[nt][2] - mn1);
                float p11 = __expf(sacc[nt][3] - mn1);
                sacc[nt][0] = p00; sacc[nt][1] = p01;
                sacc[nt][2] = p10; sacc[nt][3] = p11;
                rs0 += p00 + p01; rs1 += p10 + p11;
            }
            rs0 += __shfl_xor_sync(0xFFFFFFFFu, rs0, 1);
            rs0 += __shfl_xor_sync(0xFFFFFFFFu, rs0, 2);
            rs1 += __shfl_xor_sync(0xFFFFFFFFu, rs1, 1);
            rs1 += __shfl_xor_sync(0xFFFFFFFFu, rs1, 2);
            l0 = l0 * al0 + rs0;
            l1 = l1 * al1 + rs1;

            #pragma unroll
            for (int nt = 0; nt < 8; nt++) {
                oacc[nt][0] *= al0; oacc[nt][1] *= al0;
                oacc[nt][2] *= al1; oacc[nt][3] *= al1;
            }

            // ---- O += P V ----
            #pragma unroll
            for (int u = 0; u < 4; u++) {
                uint32_t Ph[4], Pl[4];
                #pragma unroll
                for (int half = 0; half < 2; half++) {
                    const float* pa = sacc[2 * u + half];
                    float h0 = __bfloat162float(__float2bfloat16_rn(pa[0]));
                    float h1 = __bfloat162float(__float2bfloat16_rn(pa[1]));
                    float h2 = __bfloat162float(__float2bfloat16_rn(pa[2]));
                    float h3 = __bfloat162float(__float2bfloat16_rn(pa[3]));
                    Ph[half * 2 + 0] = pack_bf2(pa[0], pa[1]);
                    Ph[half * 2 + 1] = pack_bf2(pa[2], pa[3]);
                    Pl[half * 2 + 0] = pack_bf2(pa[0] - h0, pa[1] - h1);
                    Pl[half * 2 + 1] = pack_bf2(pa[2] - h2, pa[3] - h3);
                }
                #pragma unroll
                for (int pp = 0; pp < 4; pp++) {
                    uint32_t tvh[4], tvl[4];
                    ldsm4t(tvh, vbh + (uint32_t)(u * 16 * SST * 2 + pp * 32));
                    ldsm4t(tvl, vbl + (uint32_t)(u * 16 * SST * 2 + pp * 32));
                    mma16816(oacc[2 * pp + 0], Ph, tvh);
                    mma16816(oacc[2 * pp + 1], Ph, tvh + 2);
                    mma16816(oacc[2 * pp + 0], Ph, tvl);
                    mma16816(oacc[2 * pp + 1], Ph, tvl + 2);
                    mma16816(oacc[2 * pp + 0], Pl, tvh);
                    mma16816(oacc[2 * pp + 1], Pl, tvh + 2);
                }
            }
            __syncthreads();
        }

        // ---- epilogue ----
        const int ccol = 2 * (lane & 3);
        if (gq0 < CTX_) {
            float inv = 1.f / l0;
            size_t base = (size_t)(b * CTX_ + gq0) * D_ + h * DH_ + ccol;
            #pragma unroll
            for (int nt = 0; nt < 8; nt++) {
                float v0 = oacc[nt][0] * inv, v1 = oacc[nt][1] * inv;
                float t0 = __bfloat162float(__float2bfloat16_rn(v0));
                float t1 = __bfloat162float(__float2bfloat16_rn(v1));
                *(uint32_t*)(g_AOh + base + nt * 8) = pack_bf2(v0, v1);
                *(uint32_t*)(g_AOl + base + nt * 8) = pack_bf2(v0 - t0, v1 - t1);
            }
        }
        if (gq1 < CTX_) {
            float inv = 1.f / l1;
            size_t base = (size_t)(b * CTX_ + gq1) * D_ + h * DH_ + ccol;
            #pragma unroll
            for (int nt = 0; nt < 8; nt++) {
                float v0 = oacc[nt][2] * inv, v1 = oacc[nt][3] * inv;
                float t0 = __bfloat162float(__float2bfloat16_rn(v0));
                float t1 = __bfloat162float(__float2bfloat16_rn(v1));
                *(uint32_t*)(g_AOh + base + nt * 8) = pack_bf2(v0, v1);
                *(uint32_t*)(g_AOl + base + nt * 8) = pack_bf2(v0 - t0, v1 - t1);
            }
        }
        __syncthreads();   // stage buffers reused by next pass
    }
}

// ---------------------------------------------------------------------------
extern "C" void kernel_launch(void* const* d_in, const int* in_sizes, int n_in,
                              void* d_out, int out_size) {
    const float* x  = (const float*)d_in[0];
    const float* Wq = (const float*)d_in[1];
    const float* Wk = (const float*)d_in[2];
    const float* Wv = (const float*)d_in[3];
    const float* Wo = (const float*)d_in[4];
    float* out = (float*)d_out;

    cudaFuncSetAttribute(gemm_mma, cudaFuncAttributeMaxDynamicSharedMemorySize, GSMEM);
    cudaFuncSetAttribute(attn_mma, cudaFuncAttributeMaxDynamicSharedMemorySize, ASMEM);

    // 1. Prep (gather+split x, zero-fill dead rows) + weight transpose/split
    prep_x<<<B_ * XR_, 256>>>(x, out);
    prep_w<<<dim3(D_ / 32, D_ / 64, 4), dim3(32, 8)>>>(Wq, Wk, Wv, Wo);

    // 2. Q/K/V projections -> bf16 hi/lo (Q pre-scaled by 0.125)
    gemm_mma<<<dim3(D_ / GN, (MTOT_ + GM - 1) / GM, 3), 256, GSMEM>>>(0, nullptr);

    // 3. Flash attention on tensor cores (paired q-tiles, double-buffered)
    attn_mma<<<dim3(NPAIR, H_, B_), 128, ASMEM>>>();

    // 4. Output projection, scattered to live rows
    gemm_mma<<<dim3(D_ / GN, (MTOT_ + GM - 1) / GM, 1), 256, GSMEM>>>(3, out);
}

// round 14
// speedup vs baseline: 3.6959x; 1.3491x over previous
#include <cuda_runtime.h>
#include <cuda_fp16.h>
#include <cstdint>

#define B_    4
#define T_    4096
#define D_    1024
#define H_    16
#define DH_   64
#define NS_   4
#define CTX_  516
#define Q0_   3580
#define MTOT_ (B_*CTX_)   // 2064
#define XR_   520         // per-batch gathered x rows: 4 sinks + 516 window

// ---------------------------------------------------------------------------
// Device scratch (no allocation allowed). A-side operands: fp16 hi only.
// B-side operands (weights, K, V): fp16 hi+lo.
// ---------------------------------------------------------------------------
__device__ __align__(16) __half g_Xh[B_*XR_*D_];
__device__ __align__(16) __half g_Wth[4*D_*D_];   // W^T hi: [z][n][k]
__device__ __align__(16) __half g_Wtl[4*D_*D_];   // W^T lo
__device__ __align__(16) __half g_Qh[MTOT_*D_];   // Q (pre-scaled by 0.125)
__device__ __align__(16) __half g_Kh[MTOT_*D_];
__device__ __align__(16) __half g_Kl[MTOT_*D_];
__device__ __align__(16) __half g_Vh[MTOT_*D_];
__device__ __align__(16) __half g_Vl[MTOT_*D_];
__device__ __align__(16) __half g_AOh[MTOT_*D_];

// ---------------------------------------------------------------------------
__device__ __forceinline__ uint32_t smem_u32(const void* p) {
    uint32_t a;
    asm("{ .reg .u64 t; cvta.to.shared.u64 t, %1; cvt.u32.u64 %0, t; }" : "=r"(a) : "l"(p));
    return a;
}
// pack two fp32 -> half2 (a in low, b in high)
__device__ __forceinline__ uint32_t pack_hf2(float a, float b) {
    uint32_t r;
    asm("cvt.rn.f16x2.f32 %0, %1, %2;" : "=r"(r) : "f"(b), "f"(a));
    return r;
}
__device__ __forceinline__ void ldsm4(uint32_t* r, uint32_t addr) {
    asm volatile("ldmatrix.sync.aligned.m8n8.x4.shared.b16 {%0,%1,%2,%3}, [%4];"
        : "=r"(r[0]), "=r"(r[1]), "=r"(r[2]), "=r"(r[3]) : "r"(addr));
}
__device__ __forceinline__ void ldsm4t(uint32_t* r, uint32_t addr) {
    asm volatile("ldmatrix.sync.aligned.m8n8.x4.trans.shared.b16 {%0,%1,%2,%3}, [%4];"
        : "=r"(r[0]), "=r"(r[1]), "=r"(r[2]), "=r"(r[3]) : "r"(addr));
}
__device__ __forceinline__ void mma16816(float* c, const uint32_t* a, const uint32_t* b) {
    asm volatile(
        "mma.sync.aligned.m16n8k16.row.col.f32.f16.f16.f32 "
        "{%0,%1,%2,%3}, {%4,%5,%6,%7}, {%8,%9}, {%0,%1,%2,%3};"
        : "+f"(c[0]), "+f"(c[1]), "+f"(c[2]), "+f"(c[3])
        : "r"(a[0]), "r"(a[1]), "r"(a[2]), "r"(a[3]), "r"(b[0]), "r"(b[1]));
}
__device__ __forceinline__ void cpa16(uint32_t dst, const void* src, bool valid) {
    int sz = valid ? 16 : 0;
    asm volatile("cp.async.cg.shared.global [%0], [%1], 16, %2;"
        :: "r"(dst), "l"(src), "r"(sz) : "memory");
}
#define CPA_COMMIT() asm volatile("cp.async.commit_group;" ::: "memory")
#define CPA_WAIT(n)  asm volatile("cp.async.wait_group %0;" :: "n"(n) : "memory")

// ---------------------------------------------------------------------------
// prep_x: gather live x rows -> fp16 (hi only); zero-fill dead output rows.
// ---------------------------------------------------------------------------
__global__ __launch_bounds__(256) void prep_x(const float* __restrict__ x,
                                              float* __restrict__ out) {
    int gr = blockIdx.x;
    int b = gr / XR_, r = gr % XR_;
    int tok = (r < NS_) ? r : (Q0_ + (r - NS_));
    int t = threadIdx.x;
    float4 v = *(const float4*)(x + (size_t)(b * T_ + tok) * D_ + t * 4);
    uint2 hw = make_uint2(pack_hf2(v.x, v.y), pack_hf2(v.z, v.w));
    ((uint2*)g_Xh)[(size_t)gr * 256 + t] = hw;

    const size_t nz4 = (size_t)B_ * Q0_ * D_ / 4;
    const size_t stride = (size_t)B_ * XR_ * 256;
    const size_t perb = (size_t)Q0_ * D_;
    for (size_t i = (size_t)gr * 256 + t; i < nz4; i += stride) {
        size_t e = i * 4;
        size_t bb = e / perb, rr = e % perb;
        *(float4*)(out + bb * (size_t)T_ * D_ + rr) = make_float4(0.f, 0.f, 0.f, 0.f);
    }
}

// ---------------------------------------------------------------------------
// prep_w: transpose W (4 matrices) -> [n][k] fp16 hi/lo
// ---------------------------------------------------------------------------
__global__ __launch_bounds__(256) void prep_w(
    const float* __restrict__ Wq, const float* __restrict__ Wk,
    const float* __restrict__ Wv, const float* __restrict__ Wo)
{
    const int z = blockIdx.z;
    const float* __restrict__ W = (z == 0) ? Wq : (z == 1) ? Wk : (z == 2) ? Wv : Wo;
    __shared__ float tile[64][33];
    const int n0 = blockIdx.x * 32, k0 = blockIdx.y * 64;
    const int tx = threadIdx.x, ty = threadIdx.y;

    #pragma unroll
    for (int rr = 0; rr < 8; rr++) {
        int kk = ty + rr * 8;
        tile[kk][tx] = W[(size_t)(k0 + kk) * D_ + n0 + tx];
    }
    __syncthreads();
    #pragma unroll
    for (int rr = 0; rr < 4; rr++) {
        int n = ty + rr * 8;
        float v0 = tile[tx * 2][n], v1 = tile[tx * 2 + 1][n];
        float h0 = __half2float(__float2half_rn(v0));
        float h1 = __half2float(__float2half_rn(v1));
        size_t base = (size_t)z * D_ * D_ + (size_t)(n0 + n) * D_ + k0;
        ((uint32_t*)(g_Wth + base))[tx] = pack_hf2(v0, v1);
        ((uint32_t*)(g_Wtl + base))[tx] = pack_hf2(v0 - h0, v1 - h1);
    }
}

// ---------------------------------------------------------------------------
// Tensor-core GEMM: C = Ah*(Bh+Bl), fp16, 2 MMA passes.
// modes 0/1/2 -> Q(hi) / K(hi+lo) / V(hi+lo); mode 3 -> final out (fp32).
// ---------------------------------------------------------------------------
#define GM 128
#define GN 128
#define KC 32
#define SPAD 40
#define NCHUNK (D_/KC)
#define STG  (GM*SPAD)
#define STGB (STG*2)
#define GSMEM (6*STG*2)               // 3 arrays x 2 stages = 61440 bytes

__global__ __launch_bounds__(256, 2) void gemm_mma(int mode_base, float* __restrict__ outF) {
    extern __shared__ __half ds[];
    __half* sAh = ds;
    __half* sBh = ds + 2 * STG;
    __half* sBl = ds + 4 * STG;

    const int mode = mode_base + blockIdx.z;
    const int n0 = blockIdx.x * GN;
    const int m0 = blockIdx.y * GM;
    const int tid = threadIdx.x;
    const int wid = tid >> 5, lane = tid & 31;
    const int warp_m = (wid & 1) * 64;
    const int warp_n = (wid >> 1) * 32;

    const __half* __restrict__ Bh_g = g_Wth + (size_t)mode * D_ * D_;
    const __half* __restrict__ Bl_g = g_Wtl + (size_t)mode * D_ * D_;
    const __half* __restrict__ Ah_g = (mode < 3) ? g_Xh : g_AOh;

    const int ar0 = tid >> 2, ar1 = ar0 + 64;
    const int q = tid & 3;
    long asrc0 = -1, asrc1 = -1;
    {
        int m = m0 + ar0;
        if (m < MTOT_) {
            if (mode < 3) { int b = m / CTX_, i = m % CTX_; asrc0 = (long)b * XR_ + ((mode == 0) ? (NS_ + i) : ((i < NS_) ? i : (NS_ + i))); }
            else asrc0 = m;
        }
        m = m0 + ar1;
        if (m < MTOT_) {
            if (mode < 3) { int b = m / CTX_, i = m % CTX_; asrc1 = (long)b * XR_ + ((mode == 0) ? (NS_ + i) : ((i < NS_) ? i : (NS_ + i))); }
            else asrc1 = m;
        }
    }
    const int so0 = ar0 * SPAD + q * 8;
    const int so1 = ar1 * SPAD + q * 8;
    const uint32_t dAh0 = smem_u32(sAh + so0), dAh1 = smem_u32(sAh + so1);
    const uint32_t dBh0 = smem_u32(sBh + so0), dBh1 = smem_u32(sBh + so1);
    const uint32_t dBl0 = smem_u32(sBl + so0), dBl1 = smem_u32(sBl + so1);

    const int a_row = (lane & 15), a_kh = (lane >> 4) << 3;
    uint32_t aAh[4];
    #pragma unroll
    for (int mt = 0; mt < 4; mt++) {
        int r = warp_m + mt * 16 + a_row;
        aAh[mt] = smem_u32(sAh + r * SPAD + a_kh);
    }
    const int b_row = (lane & 7) + ((lane >> 4) & 1) * 8;
    const int b_k   = ((lane >> 3) & 1) * 8;
    uint32_t bB01h, bB01l, bB23h, bB23l;
    {
        int r01 = warp_n + b_row, r23 = warp_n + 16 + b_row;
        bB01h = smem_u32(sBh + r01 * SPAD + b_k);
        bB01l = smem_u32(sBl + r01 * SPAD + b_k);
        bB23h = smem_u32(sBh + r23 * SPAD + b_k);
        bB23l = smem_u32(sBl + r23 * SPAD + b_k);
    }

    float acc[4][4][4];
    #pragma unroll
    for (int a = 0; a < 4; a++)
        #pragma unroll
        for (int b = 0; b < 4; b++)
            #pragma unroll
            for (int cc = 0; cc < 4; cc++) acc[a][b][cc] = 0.f;

    auto issue = [&](int c) {
        const uint32_t so = (uint32_t)(c & 1) * STGB;
        const size_t koff = (size_t)c * KC + q * 8;
        const size_t a0 = (asrc0 >= 0 ? (size_t)asrc0 : 0) * D_ + koff;
        const size_t a1 = (asrc1 >= 0 ? (size_t)asrc1 : 0) * D_ + koff;
        cpa16(dAh0 + so, Ah_g + a0, asrc0 >= 0);
        cpa16(dAh1 + so, Ah_g + a1, asrc1 >= 0);
        cpa16(dBh0 + so, Bh_g + (size_t)(n0 + ar0) * D_ + koff, true);
        cpa16(dBh1 + so, Bh_g + (size_t)(n0 + ar1) * D_ + koff, true);
        cpa16(dBl0 + so, Bl_g + (size_t)(n0 + ar0) * D_ + koff, true);
        cpa16(dBl1 + so, Bl_g + (size_t)(n0 + ar1) * D_ + koff, true);
        CPA_COMMIT();
    };

    issue(0);
    issue(1);
    for (int c = 0; c < NCHUNK; c++) {
        if (c == NCHUNK - 1) { CPA_WAIT(0); } else { CPA_WAIT(1); }
        __syncthreads();
        const uint32_t so = (uint32_t)(c & 1) * STGB;
        #pragma unroll
        for (int ks = 0; ks < KC * 2; ks += 32) {
            uint32_t fBh[4][2], fBl[4][2], t4[4];
            ldsm4(t4, bB01h + so + ks);
            fBh[0][0] = t4[0]; fBh[0][1] = t4[1]; fBh[1][0] = t4[2]; fBh[1][1] = t4[3];
            ldsm4(t4, bB23h + so + ks);
            fBh[2][0] = t4[0]; fBh[2][1] = t4[1]; fBh[3][0] = t4[2]; fBh[3][1] = t4[3];
            ldsm4(t4, bB01l + so + ks);
            fBl[0][0] = t4[0]; fBl[0][1] = t4[1]; fBl[1][0] = t4[2]; fBl[1][1] = t4[3];
            ldsm4(t4, bB23l + so + ks);
            fBl[2][0] = t4[0]; fBl[2][1] = t4[1]; fBl[3][0] = t4[2]; fBl[3][1] = t4[3];

            #pragma unroll
            for (int mp = 0; mp < 2; mp++) {
                const int mt0 = mp * 2, mt1 = mp * 2 + 1;
                uint32_t fA0[4], fA1[4];
                ldsm4(fA0, aAh[mt0] + so + ks);
                ldsm4(fA1, aAh[mt1] + so + ks);
                #pragma unroll
                for (int nt = 0; nt < 4; nt++) mma16816(acc[mt0][nt], fA0, fBh[nt]);
                #pragma unroll
                for (int nt = 0; nt < 4; nt++) mma16816(acc[mt1][nt], fA1, fBh[nt]);
                #pragma unroll
                for (int nt = 0; nt < 4; nt++) mma16816(acc[mt0][nt], fA0, fBl[nt]);
                #pragma unroll
                for (int nt = 0; nt < 4; nt++) mma16816(acc[mt1][nt], fA1, fBl[nt]);
            }
        }
        __syncthreads();
        if (c + 2 < NCHUNK) issue(c + 2);
    }

    const int er = lane >> 2, ec = (lane & 3) * 2;
    if (mode < 3) {
        __half* dh = (mode == 0) ? g_Qh : (mode == 1) ? g_Kh : g_Vh;
        __half* dl = (mode == 1) ? g_Kl : g_Vl;        // unused when mode==0
        const bool wlo = (mode != 0);
        const float scl = (mode == 0) ? 0.125f : 1.0f;
        #pragma unroll
        for (int mt = 0; mt < 4; mt++) {
            #pragma unroll
            for (int half = 0; half < 2; half++) {
                int mm = m0 + warp_m + mt * 16 + er + half * 8;
                if (mm < MTOT_) {
                    size_t base = (size_t)mm * D_ + n0 + warp_n + ec;
                    #pragma unroll
                    for (int nt = 0; nt < 4; nt++) {
                        float v0 = acc[mt][nt][half * 2] * scl;
                        float v1 = acc[mt][nt][half * 2 + 1] * scl;
                        *(uint32_t*)(dh + base + nt * 8) = pack_hf2(v0, v1);
                        if (wlo) {
                            float t0 = __half2float(__float2half_rn(v0));
                            float t1 = __half2float(__float2half_rn(v1));
                            *(uint32_t*)(dl + base + nt * 8) = pack_hf2(v0 - t0, v1 - t1);
                        }
                    }
                }
            }
        }
    } else {
        #pragma unroll
        for (int mt = 0; mt < 4; mt++) {
            #pragma unroll
            for (int half = 0; half < 2; half++) {
                int mm = m0 + warp_m + mt * 16 + er + half * 8;
                if (mm < MTOT_) {
                    int b = mm / CTX_, i = mm % CTX_;
                    float* dst = outF + (size_t)(b * T_ + Q0_ + i) * D_ + n0;
                    #pragma unroll
                    for (int nt = 0; nt < 4; nt++) {
                        float2 v = make_float2(acc[mt][nt][half * 2], acc[mt][nt][half * 2 + 1]);
                        *(float2*)(dst + warp_n + nt * 8 + ec) = v;
                    }
                }
            }
        }
    }
}

// ---------------------------------------------------------------------------
// Flash attention (fp16): S = Qh*(Kh+Kl), O += Ph*(Vh+Vl).
// cp.async double-buffered, tile-paired blocks, 128 threads.
// ---------------------------------------------------------------------------
#define SST   72
#define TILEH (64*SST)
#define NTILE ((CTX_ + 63) / 64)       // 9
#define TMAX  (NTILE - 1)              // 8
#define NPAIR ((NTILE + 1) / 2)        // 5
#define ASMEM (2 * 4 * TILEH * 2)      // 73728 bytes

__global__ __launch_bounds__(128) void attn_mma() {
    extern __shared__ __half as_[];
    const int b = blockIdx.z, h = blockIdx.y, p = blockIdx.x;
    const int tid = threadIdx.x, warp = tid >> 5, lane = tid & 31;

    const uint32_t sbase = smem_u32(as_);
    const __half* __restrict__ KVsrc[4] = { g_Kh, g_Kl, g_Vh, g_Vl };

    const int srow = tid >> 3;
    const int sdd  = (tid & 7) * 8;

    const uint32_t k4o = (uint32_t)((((lane & 7) + ((lane >> 4) & 1) * 8) * SST + ((lane >> 3) & 1) * 8) * 2);
    const uint32_t v4o = (uint32_t)((((lane & 7) + ((lane >> 3) & 1) * 8) * SST) * 2 + ((lane >> 4) & 1) * 16);
    const uint32_t qfo = (uint32_t)((warp * 16 + (lane & 15)) * (SST * 2) + ((lane >> 4) & 1) * 16);

    const int npass = (2 * p == TMAX) ? 1 : 2;
    for (int pass = 0; pass < npass; pass++) {
        const int tau = (pass == 0) ? p : (TMAX - p);
        const int gq0 = tau * 64 + warp * 16 + (lane >> 2);
        const int gq1 = gq0 + 8;

        // ---- stage Q into stage0 array0, extract frags ----
        const uint4 zv = make_uint4(0, 0, 0, 0);
        for (int it = tid; it < 64 * 8; it += 128) {
            int row = it >> 3, dd = (it & 7) * 8;
            int gq = tau * 64 + row;
            uint4 vh = zv;
            if (gq < CTX_) {
                size_t off = (size_t)(b * CTX_ + gq) * D_ + h * DH_ + dd;
                vh = *(const uint4*)(g_Qh + off);
            }
            *(uint4*)(as_ + row * SST + dd) = vh;
        }
        __syncthreads();
        uint32_t QhF[4][4];
        #pragma unroll
        for (int ks = 0; ks < 4; ks++)
            ldsm4(QhF[ks], sbase + qfo + ks * 32);
        __syncthreads();

        float oacc[8][4];
        #pragma unroll
        for (int nt = 0; nt < 8; nt++)
            #pragma unroll
            for (int c = 0; c < 4; c++) oacc[nt][c] = 0.f;
        float m0 = -1e30f, m1 = -1e30f, l0 = 0.f, l1 = 0.f;

        auto issueTile = [&](int t, int s) {
            #pragma unroll
            for (int rr = 0; rr < 4; rr++) {
                int row = srow + rr * 16;
                int j = t * 64 + row;
                bool v = (j < CTX_);
                size_t off = (size_t)(b * CTX_ + (v ? j : 0)) * D_ + h * DH_ + sdd;
                uint32_t dst = sbase + (uint32_t)(((s * 4) * TILEH + row * SST + sdd) * 2);
                #pragma unroll
                for (int a = 0; a < 4; a++)
                    cpa16(dst + (uint32_t)(a * TILEH * 2), KVsrc[a] + off, v);
            }
            CPA_COMMIT();
        };

        issueTile(0, 0);
        for (int t = 0; t <= tau; t++) {
            if (t + 1 <= tau) { issueTile(t + 1, (t + 1) & 1); CPA_WAIT(1); }
            else              { CPA_WAIT(0); }
            __syncthreads();
            const uint32_t sb = sbase + (uint32_t)((t & 1) * 4 * TILEH * 2);
            const uint32_t kbh = sb + 0 * TILEH * 2 + k4o;
            const uint32_t kbl = sb + 1 * TILEH * 2 + k4o;
            const uint32_t vbh = sb + 2 * TILEH * 2 + v4o;
            const uint32_t vbl = sb + 3 * TILEH * 2 + v4o;

            // ---- S = Qh (Kh + Kl)^T ----
            float sacc[8][4];
            #pragma unroll
            for (int nt = 0; nt < 8; nt++)
                #pragma unroll
                for (int c = 0; c < 4; c++) sacc[nt][c] = 0.f;

            #pragma unroll
            for (int ks = 0; ks < 4; ks++) {
                #pragma unroll
                for (int pp = 0; pp < 4; pp++) {
                    uint32_t th[4], tl[4];
                    ldsm4(th, kbh + (uint32_t)(pp * 16 * SST * 2 + ks * 32));
                    ldsm4(tl, kbl + (uint32_t)(pp * 16 * SST * 2 + ks * 32));
                    mma16816(sacc[2 * pp + 0], QhF[ks], th);
                    mma16816(sacc[2 * pp + 1], QhF[ks], th + 2);
                    mma16816(sacc[2 * pp + 0], QhF[ks], tl);
                    mma16816(sacc[2 * pp + 1], QhF[ks], tl + 2);
                }
            }

            // ---- causal mask (diagonal tile only) ----
            if (t == tau) {
                const int cbase = t * 64 + 2 * (lane & 3);
                #pragma unroll
                for (int nt = 0; nt < 8; nt++) {
                    int c0 = cbase + nt * 8, c1 = c0 + 1;
                    if (c0 > gq0) sacc[nt][0] = -1e30f;
                    if (c1 > gq0) sacc[nt][1] = -1e30f;
                    if (c0 > gq1) sacc[nt][2] = -1e30f;
                    if (c1 > gq1) sacc[nt][3] = -1e30f;
                }
            }

            // ---- online softmax ----
            float mx0 = -1e30f, mx1 = -1e30f;
            #pragma unroll
            for (int nt = 0; nt < 8; nt++) {
                mx0 = fmaxf(mx0, fmaxf(sacc[nt][0], sacc[nt][1]));
                mx1 = fmaxf(mx1, fmaxf(sacc[nt][2], sacc[nt][3]));
            }
            mx0 = fmaxf(mx0, __shfl_xor_sync(0xFFFFFFFFu, mx0, 1));
            mx0 = fmaxf(mx0, __shfl_xor_sync(0xFFFFFFFFu, mx0, 2));
            mx1 = fmaxf(mx1, __shfl_xor_sync(0xFFFFFFFFu, mx1, 1));
            mx1 = fmaxf(mx1, __shfl_xor_sync(0xFFFFFFFFu, mx1, 2));
            float mn0 = fmaxf(m0, mx0), mn1 = fmaxf(m1, mx1);
            float al0 = __expf(m0 - mn0), al1 = __expf(m1 - mn1);
            m0 = mn0; m1 = mn1;

            float rs0 = 0.f, rs1 = 0.f;
            #pragma unroll
            for (int nt = 0; nt < 8; nt++) {
                float p00 = __expf(sacc[nt][0] - mn0);
                float p01 = __expf(sacc[nt][1] - mn0);
                float p10 = __expf(sacc[nt][2] - mn1);
                float p11 = __expf(sacc[nt][3] - mn1);
                sacc[nt][0] = p00; sacc[nt][1] = p01;
                sacc[nt][2] = p10; sacc[nt][3] = p11;
                rs0 += p00 + p01; rs1 += p10 + p11;
            }
            rs0 += __shfl_xor_sync(0xFFFFFFFFu, rs0, 1);
            rs0 += __shfl_xor_sync(0xFFFFFFFFu, rs0, 2);
            rs1 += __shfl_xor_sync(0xFFFFFFFFu, rs1, 1);
            rs1 += __shfl_xor_sync(0xFFFFFFFFu, rs1, 2);
            l0 = l0 * al0 + rs0;
            l1 = l1 * al1 + rs1;

            #pragma unroll
            for (int nt = 0; nt < 8; nt++) {
                oacc[nt][0] *= al0; oacc[nt][1] *= al0;
                oacc[nt][2] *= al1; oacc[nt][3] *= al1;
            }

            // ---- O += Ph (Vh + Vl) ----
            #pragma unroll
            for (int u = 0; u < 4; u++) {
                uint32_t Ph[4];
                #pragma unroll
                for (int half = 0; half < 2; half++) {
                    const float* pa = sacc[2 * u + half];
                    Ph[half * 2 + 0] = pack_hf2(pa[0], pa[1]);
                    Ph[half * 2 + 1] = pack_hf2(pa[2], pa[3]);
                }
                #pragma unroll
                for (int pp = 0; pp < 4; pp++) {
                    uint32_t tvh[4], tvl[4];
                    ldsm4t(tvh, vbh + (uint32_t)(u * 16 * SST * 2 + pp * 32));
                    ldsm4t(tvl, vbl + (uint32_t)(u * 16 * SST * 2 + pp * 32));
                    mma16816(oacc[2 * pp + 0], Ph, tvh);
                    mma16816(oacc[2 * pp + 1], Ph, tvh + 2);
                    mma16816(oacc[2 * pp + 0], Ph, tvl);
                    mma16816(oacc[2 * pp + 1], Ph, tvl + 2);
                }
            }
            __syncthreads();
        }

        // ---- epilogue: normalize, write fp16 AO (hi only) ----
        const int ccol = 2 * (lane & 3);
        if (gq0 < CTX_) {
            float inv = 1.f / l0;
            size_t base = (size_t)(b * CTX_ + gq0) * D_ + h * DH_ + ccol;
            #pragma unroll
            for (int nt = 0; nt < 8; nt++)
                *(uint32_t*)(g_AOh + base + nt * 8) =
                    pack_hf2(oacc[nt][0] * inv, oacc[nt][1] * inv);
        }
        if (gq1 < CTX_) {
            float inv = 1.f / l1;
            size_t base = (size_t)(b * CTX_ + gq1) * D_ + h * DH_ + ccol;
            #pragma unroll
            for (int nt = 0; nt < 8; nt++)
                *(uint32_t*)(g_AOh + base + nt * 8) =
                    pack_hf2(oacc[nt][2] * inv, oacc[nt][3] * inv);
        }
        __syncthreads();
    }
}

// ---------------------------------------------------------------------------
extern "C" void kernel_launch(void* const* d_in, const int* in_sizes, int n_in,
                              void* d_out, int out_size) {
    const float* x  = (const float*)d_in[0];
    const float* Wq = (const float*)d_in[1];
    const float* Wk = (const float*)d_in[2];
    const float* Wv = (const float*)d_in[3];
    const float* Wo = (const float*)d_in[4];
    float* out = (float*)d_out;

    cudaFuncSetAttribute(gemm_mma, cudaFuncAttributeMaxDynamicSharedMemorySize, GSMEM);
    cudaFuncSetAttribute(attn_mma, cudaFuncAttributeMaxDynamicSharedMemorySize, ASMEM);

    // 1. Prep (gather x -> fp16, zero-fill dead rows) + weight transpose/split
    prep_x<<<B_ * XR_, 256>>>(x, out);
    prep_w<<<dim3(D_ / 32, D_ / 64, 4), dim3(32, 8)>>>(Wq, Wk, Wv, Wo);

    // 2. Q/K/V projections (Q pre-scaled by 0.125)
    gemm_mma<<<dim3(D_ / GN, (MTOT_ + GM - 1) / GM, 3), 256, GSMEM>>>(0, nullptr);

    // 3. Flash attention on tensor cores
    attn_mma<<<dim3(NPAIR, H_, B_), 128, ASMEM>>>();

    // 4. Output projection, scattered to live rows
    gemm_mma<<<dim3(D_ / GN, (MTOT_ + GM - 1) / GM, 1), 256, GSMEM>>>(3, out);
}